// round 2
// baseline (speedup 1.0000x reference)
#include <cuda_runtime.h>
#include <math.h>

#define Bb 4
#define LQ 640
#define LIMt 1296
#define LKt 1936
#define DM 768
#define NH 12
#define DKh 64
#define DFFn 3072
#define MD 100

// ---------------- scratch (device globals: allocation-guard safe) ----------------
__device__ float g_full[Bb*LKt*DM];
__device__ float g_q   [Bb*LQ*DM];
__device__ float g_k   [Bb*LKt*DM];
__device__ float g_v   [Bb*LKt*DM];
__device__ float g_ctx [Bb*LQ*DM];
__device__ float g_tmp [Bb*LQ*DM];   // attn_out, later ffn2
__device__ float g_src1[Bb*LQ*DM];
__device__ float g_ffn1[Bb*LQ*DFFn];

// ---------------- concat: full = [im_tokens, docqa] ----------------
__global__ void concat_kernel(const float* __restrict__ im, const float* __restrict__ doc,
                              float* __restrict__ full) {
    size_t idx = (size_t)blockIdx.x * blockDim.x + threadIdx.x;
    const size_t total = (size_t)Bb*LKt*DM;
    if (idx >= total) return;
    size_t bt = idx / DM; int d = (int)(idx % DM);
    int b = (int)(bt / LKt); int t = (int)(bt % LKt);
    float v;
    if (t < LIMt) v = im[((size_t)b*LIMt + t)*DM + d];
    else          v = doc[((size_t)b*LQ + (t - LIMt))*DM + d];
    full[idx] = v;
}

// ---------------- generic tiled GEMM: C = A[MxK] @ W[KxN] + bias, opt ReLU ----------------
template<bool RELU>
__global__ void __launch_bounds__(256) gemm_bias_kernel(
    const float* __restrict__ A, const float* __restrict__ W,
    const float* __restrict__ bias, float* __restrict__ C,
    int M, int N, int K)
{
    __shared__ float As[16][68];   // As[k][m]
    __shared__ float Bs[16][68];   // Bs[k][n]
    const int tid = threadIdx.x;
    const int tx = tid & 15, ty = tid >> 4;
    const int m0 = blockIdx.y * 64, n0 = blockIdx.x * 64;

    float acc[4][4];
    #pragma unroll
    for (int i=0;i<4;i++) { acc[i][0]=0.f; acc[i][1]=0.f; acc[i][2]=0.f; acc[i][3]=0.f; }

    for (int k0 = 0; k0 < K; k0 += 16) {
        #pragma unroll
        for (int i=0;i<4;i++) {
            int e = tid + 256*i;
            int r = e >> 4, c = e & 15;
            As[c][r] = A[(size_t)(m0 + r) * K + k0 + c];
        }
        #pragma unroll
        for (int i=0;i<4;i++) {
            int e = tid + 256*i;
            int r = e >> 6, c = e & 63;
            Bs[r][c] = W[(size_t)(k0 + r) * N + n0 + c];
        }
        __syncthreads();
        #pragma unroll
        for (int k=0;k<16;k++) {
            float4 a4 = *(const float4*)&As[k][ty*4];
            float4 b4 = *(const float4*)&Bs[k][tx*4];
            float a[4] = {a4.x,a4.y,a4.z,a4.w};
            float b[4] = {b4.x,b4.y,b4.z,b4.w};
            #pragma unroll
            for (int i=0;i<4;i++)
                #pragma unroll
                for (int j=0;j<4;j++)
                    acc[i][j] = fmaf(a[i], b[j], acc[i][j]);
        }
        __syncthreads();
    }
    #pragma unroll
    for (int i=0;i<4;i++) {
        int row = m0 + ty*4 + i;
        #pragma unroll
        for (int j=0;j<4;j++) {
            int col = n0 + tx*4 + j;
            float v = acc[i][j] + bias[col];
            if (RELU) v = fmaxf(v, 0.f);
            C[(size_t)row * N + col] = v;
        }
    }
}

// ---------------- flash attention with relative-position bias ----------------
struct AttnSmem {
    float Qs[64][65];
    float Ks[64][65];
    float Vs[64][65];
    float Ps[64][65];
    float red1[64][8];
    float red2[64][8];
    float bx[201];
    float by[201];
    int qx[64], qy[64], kx[64], ky[64];
};

__global__ void __launch_bounds__(128) attn_kernel(
    const float* __restrict__ qb, const float* __restrict__ kb_, const float* __restrict__ vb_,
    const int* __restrict__ dqx, const int* __restrict__ dqy,
    const int* __restrict__ imx, const int* __restrict__ imy,
    const float* __restrict__ bias_x, const float* __restrict__ bias_y,
    float* __restrict__ ctx)
{
    extern __shared__ char smem_raw[];
    AttnSmem& S = *reinterpret_cast<AttnSmem*>(smem_raw);
    const int tid = threadIdx.x;
    const int ty = tid >> 3, tx = tid & 7;
    const int qt = blockIdx.x;           // q tile 0..9
    const int bh = blockIdx.y;           // 0..47
    const int b = bh / NH, h = bh % NH;
    const int qbase = qt * 64;
    const int r0 = ty * 4;
    const int c0 = tx * 8;

    for (int e = tid; e < 64*64; e += 128) {
        int r = e >> 6, d = e & 63;
        S.Qs[r][d] = qb[(size_t)(b*LQ + qbase + r)*DM + h*DKh + d];
    }
    for (int i = tid; i < 201; i += 128) {
        S.bx[i] = bias_x[i*NH + h];
        S.by[i] = bias_y[i*NH + h];
    }
    if (tid < 64) {
        S.qx[tid] = dqx[b*LQ + qbase + tid];
        S.qy[tid] = dqy[b*LQ + qbase + tid];
    }

    float o[4][8];
    #pragma unroll
    for (int i=0;i<4;i++)
        #pragma unroll
        for (int j=0;j<8;j++) o[i][j]=0.f;
    float mreg[4], lreg[4];
    #pragma unroll
    for (int i=0;i<4;i++){ mreg[i] = -1e30f; lreg[i] = 0.f; }

    const int NT = (LKt + 63) / 64;   // 31
    for (int kt = 0; kt < NT; kt++) {
        const int kbase = kt * 64;
        __syncthreads();   // previous-iteration consumers finished
        for (int e = tid; e < 64*64; e += 128) {
            int r = e >> 6, d = e & 63;
            int kg = kbase + r;
            float kk = 0.f, vv = 0.f;
            if (kg < LKt) {
                size_t off = (size_t)(b*LKt + kg)*DM + h*DKh + d;
                kk = kb_[off];
                vv = vb_[off];
            }
            S.Ks[r][d] = kk;
            S.Vs[r][d] = vv;
        }
        if (tid < 64) {
            int kg = kbase + tid;
            int xv = 0, yv = 0;
            if (kg < LKt) {
                if (kg < LIMt) { xv = imx[b*LIMt + kg];        yv = imy[b*LIMt + kg]; }
                else           { xv = dqx[b*LQ + kg - LIMt];   yv = dqy[b*LQ + kg - LIMt]; }
            }
            S.kx[tid] = xv; S.ky[tid] = yv;
        }
        __syncthreads();

        // S = Q @ K^T
        float s[4][8];
        #pragma unroll
        for (int i=0;i<4;i++)
            #pragma unroll
            for (int j=0;j<8;j++) s[i][j]=0.f;
        #pragma unroll 4
        for (int d=0; d<64; d++) {
            float qa[4], kreg[8];
            #pragma unroll
            for (int i=0;i<4;i++) qa[i] = S.Qs[r0+i][d];
            #pragma unroll
            for (int j=0;j<8;j++) kreg[j] = S.Ks[c0+j][d];
            #pragma unroll
            for (int i=0;i<4;i++)
                #pragma unroll
                for (int j=0;j<8;j++) s[i][j] = fmaf(qa[i], kreg[j], s[i][j]);
        }
        // scale + rel-pos bias + mask
        #pragma unroll
        for (int i=0;i<4;i++) {
            int qxv = S.qx[r0+i], qyv = S.qy[r0+i];
            #pragma unroll
            for (int j=0;j<8;j++) {
                int c = c0 + j;
                int rx = qxv - S.kx[c]; rx = rx < -MD ? -MD : (rx > MD ? MD : rx);
                int ry = qyv - S.ky[c]; ry = ry < -MD ? -MD : (ry > MD ? MD : ry);
                float val = s[i][j]*0.125f + S.bx[rx + MD] + S.by[ry + MD];
                if (kbase + c >= LKt) val = -1e30f;
                s[i][j] = val;
            }
        }
        // online softmax: row max
        #pragma unroll
        for (int i=0;i<4;i++) {
            float tm = s[i][0];
            #pragma unroll
            for (int j=1;j<8;j++) tm = fmaxf(tm, s[i][j]);
            S.red1[r0+i][tx] = tm;
        }
        __syncthreads();
        float factor[4];
        #pragma unroll
        for (int i=0;i<4;i++) {
            float nm = mreg[i];
            #pragma unroll
            for (int t=0;t<8;t++) nm = fmaxf(nm, S.red1[r0+i][t]);
            factor[i] = __expf(mreg[i] - nm);
            mreg[i] = nm;
        }
        #pragma unroll
        for (int i=0;i<4;i++) {
            float rs = 0.f;
            #pragma unroll
            for (int j=0;j<8;j++) {
                float p = __expf(s[i][j] - mreg[i]);
                S.Ps[r0+i][c0+j] = p;
                rs += p;
            }
            S.red2[r0+i][tx] = rs;
            #pragma unroll
            for (int j=0;j<8;j++) o[i][j] *= factor[i];
        }
        __syncthreads();
        #pragma unroll
        for (int i=0;i<4;i++) {
            float rs = 0.f;
            #pragma unroll
            for (int t=0;t<8;t++) rs += S.red2[r0+i][t];
            lreg[i] = lreg[i]*factor[i] + rs;
        }
        // O += P @ V
        #pragma unroll 4
        for (int k=0;k<64;k++) {
            float pa[4], vr[8];
            #pragma unroll
            for (int i=0;i<4;i++) pa[i] = S.Ps[r0+i][k];
            #pragma unroll
            for (int j=0;j<8;j++) vr[j] = S.Vs[k][c0+j];
            #pragma unroll
            for (int i=0;i<4;i++)
                #pragma unroll
                for (int j=0;j<8;j++) o[i][j] = fmaf(pa[i], vr[j], o[i][j]);
        }
    }
    #pragma unroll
    for (int i=0;i<4;i++) {
        float inv = 1.f / lreg[i];
        #pragma unroll
        for (int j=0;j<8;j++)
            ctx[(size_t)(b*LQ + qbase + r0 + i)*DM + h*DKh + c0 + j] = o[i][j]*inv;
    }
}

// ---------------- fused add + LayerNorm: out = LN(a + c) * g + be ----------------
__global__ void __launch_bounds__(256) addln_kernel(
    const float* __restrict__ A, const float* __restrict__ Cv,
    const float* __restrict__ g, const float* __restrict__ be,
    float* __restrict__ out)
{
    __shared__ float sred[256];
    const int row = blockIdx.x;
    const int tid = threadIdx.x;
    const size_t base = (size_t)row * DM;

    float x[3];
    #pragma unroll
    for (int i=0;i<3;i++) {
        int col = tid + 256*i;
        x[i] = A[base + col] + Cv[base + col];
    }
    float s = x[0] + x[1] + x[2];
    sred[tid] = s; __syncthreads();
    for (int off=128; off>0; off>>=1) {
        if (tid < off) sred[tid] += sred[tid+off];
        __syncthreads();
    }
    float mu = sred[0] * (1.f/DM);
    __syncthreads();
    float d0=x[0]-mu, d1=x[1]-mu, d2=x[2]-mu;
    sred[tid] = d0*d0 + d1*d1 + d2*d2; __syncthreads();
    for (int off=128; off>0; off>>=1) {
        if (tid < off) sred[tid] += sred[tid+off];
        __syncthreads();
    }
    float rs = rsqrtf(sred[0] * (1.f/DM) + 1e-5f);
    #pragma unroll
    for (int i=0;i<3;i++) {
        int col = tid + 256*i;
        out[base + col] = (x[i] - mu) * rs * g[col] + be[col];
    }
}

// ---------------- launch ----------------
extern "C" void kernel_launch(void* const* d_in, const int* in_sizes, int n_in,
                              void* d_out, int out_size) {
    const float* docqa  = (const float*)d_in[0];
    const float* im     = (const float*)d_in[1];
    const int*   dqx    = (const int*)  d_in[2];
    const int*   dqy    = (const int*)  d_in[3];
    const int*   imx    = (const int*)  d_in[4];
    const int*   imy    = (const int*)  d_in[5];
    const float* Wq     = (const float*)d_in[6];
    const float* bq     = (const float*)d_in[7];
    const float* Wk     = (const float*)d_in[8];
    const float* bk     = (const float*)d_in[9];
    const float* Wv     = (const float*)d_in[10];
    const float* bv     = (const float*)d_in[11];
    const float* Wo     = (const float*)d_in[12];
    const float* bo     = (const float*)d_in[13];
    const float* bias_x = (const float*)d_in[14];
    const float* bias_y = (const float*)d_in[15];
    const float* W1     = (const float*)d_in[16];
    const float* b1     = (const float*)d_in[17];
    const float* W2     = (const float*)d_in[18];
    const float* b2     = (const float*)d_in[19];
    const float* g1     = (const float*)d_in[20];
    const float* be1    = (const float*)d_in[21];
    const float* g2     = (const float*)d_in[22];
    const float* be2    = (const float*)d_in[23];
    float* out = (float*)d_out;

    float *p_full, *p_q, *p_k, *p_v, *p_ctx, *p_tmp, *p_src1, *p_ffn1;
    cudaGetSymbolAddress((void**)&p_full, g_full);
    cudaGetSymbolAddress((void**)&p_q,    g_q);
    cudaGetSymbolAddress((void**)&p_k,    g_k);
    cudaGetSymbolAddress((void**)&p_v,    g_v);
    cudaGetSymbolAddress((void**)&p_ctx,  g_ctx);
    cudaGetSymbolAddress((void**)&p_tmp,  g_tmp);
    cudaGetSymbolAddress((void**)&p_src1, g_src1);
    cudaGetSymbolAddress((void**)&p_ffn1, g_ffn1);

    // raise dynamic-smem limit for the attention kernel (idempotent)
    cudaFuncSetAttribute(attn_kernel, cudaFuncAttributeMaxDynamicSharedMemorySize,
                         (int)sizeof(AttnSmem));

    const int MQ = Bb*LQ;     // 2560
    const int MK = Bb*LKt;    // 7744

    {
        size_t total = (size_t)Bb*LKt*DM;
        concat_kernel<<<(unsigned)((total + 255)/256), 256>>>(im, docqa, p_full);
    }
    gemm_bias_kernel<false><<<dim3(DM/64,   MQ/64), 256>>>(docqa,  Wq, bq, p_q,   MQ, DM,  DM);
    gemm_bias_kernel<false><<<dim3(DM/64,   MK/64), 256>>>(p_full, Wk, bk, p_k,   MK, DM,  DM);
    gemm_bias_kernel<false><<<dim3(DM/64,   MK/64), 256>>>(p_full, Wv, bv, p_v,   MK, DM,  DM);

    attn_kernel<<<dim3(LQ/64, Bb*NH), 128, sizeof(AttnSmem)>>>(
        p_q, p_k, p_v, dqx, dqy, imx, imy, bias_x, bias_y, p_ctx);

    gemm_bias_kernel<false><<<dim3(DM/64,   MQ/64), 256>>>(p_ctx,  Wo, bo, p_tmp, MQ, DM,  DM);
    addln_kernel<<<MQ, 256>>>(docqa, p_tmp, g1, be1, p_src1);
    gemm_bias_kernel<true ><<<dim3(DFFn/64, MQ/64), 256>>>(p_src1, W1, b1, p_ffn1, MQ, DFFn, DM);
    gemm_bias_kernel<false><<<dim3(DM/64,   MQ/64), 256>>>(p_ffn1, W2, b2, p_tmp, MQ, DM,  DFFn);
    addln_kernel<<<MQ, 256>>>(p_src1, p_tmp, g2, be2, out);
}

// round 4
// speedup vs baseline: 1.4439x; 1.4439x over previous
#include <cuda_runtime.h>
#include <cuda_bf16.h>
#include <math.h>
#include <stdint.h>

#define Bb 4
#define LQ 640
#define LIMt 1296
#define LKt 1936
#define DM 768
#define NH 12
#define DKh 64
#define DFFn 3072
#define MD 100

// ================= helpers =================
__device__ __forceinline__ uint32_t smem_to_u32(const void* p) {
    uint32_t a;
    asm("{ .reg .u64 t; cvta.to.shared.u64 t, %1; cvt.u32.u64 %0, t; }" : "=r"(a) : "l"(p));
    return a;
}
__device__ __forceinline__ void cp_async16(uint32_t dst, const void* src, int src_bytes) {
    asm volatile("cp.async.cg.shared.global [%0], [%1], 16, %2;"
                 :: "r"(dst), "l"(src), "r"(src_bytes) : "memory");
}
__device__ __forceinline__ void cp_commit() {
    asm volatile("cp.async.commit_group;" ::: "memory");
}
template<int N>
__device__ __forceinline__ void cp_wait() {
    asm volatile("cp.async.wait_group %0;" :: "n"(N) : "memory");
}
__device__ __forceinline__ void ldm_x4(uint32_t& r0, uint32_t& r1, uint32_t& r2, uint32_t& r3,
                                       uint32_t addr) {
    asm volatile("ldmatrix.sync.aligned.m8n8.x4.shared.b16 {%0,%1,%2,%3}, [%4];"
                 : "=r"(r0), "=r"(r1), "=r"(r2), "=r"(r3) : "r"(addr));
}
__device__ __forceinline__ void mma16816(float& d0, float& d1, float& d2, float& d3,
                                         uint32_t a0, uint32_t a1, uint32_t a2, uint32_t a3,
                                         uint32_t b0, uint32_t b1) {
    asm volatile("mma.sync.aligned.m16n8k16.row.col.f32.bf16.bf16.f32 "
                 "{%0,%1,%2,%3}, {%4,%5,%6,%7}, {%8,%9}, {%0,%1,%2,%3};"
                 : "+f"(d0), "+f"(d1), "+f"(d2), "+f"(d3)
                 : "r"(a0), "r"(a1), "r"(a2), "r"(a3), "r"(b0), "r"(b1));
}

// ================= scratch =================
__device__ float g_q   [Bb*LQ*DM];
__device__ float g_k   [Bb*LKt*DM];
__device__ float g_v   [Bb*LKt*DM];
__device__ float g_tmp [Bb*LQ*DM];
__device__ float g_src1[Bb*LQ*DM];

__device__ __nv_bfloat16 g_full_h[Bb*LKt*DM], g_full_l[Bb*LKt*DM];
__device__ __nv_bfloat16 g_dq_h  [Bb*LQ*DM],  g_dq_l  [Bb*LQ*DM];
__device__ __nv_bfloat16 g_ctx_h [Bb*LQ*DM],  g_ctx_l [Bb*LQ*DM];
__device__ __nv_bfloat16 g_s1_h  [Bb*LQ*DM],  g_s1_l  [Bb*LQ*DM];
__device__ __nv_bfloat16 g_f1_h  [Bb*LQ*DFFn],g_f1_l  [Bb*LQ*DFFn];
__device__ __nv_bfloat16 g_wqt_h[DM*DM],  g_wqt_l[DM*DM];
__device__ __nv_bfloat16 g_wkt_h[DM*DM],  g_wkt_l[DM*DM];
__device__ __nv_bfloat16 g_wvt_h[DM*DM],  g_wvt_l[DM*DM];
__device__ __nv_bfloat16 g_wot_h[DM*DM],  g_wot_l[DM*DM];
__device__ __nv_bfloat16 g_w1t_h[DFFn*DM],g_w1t_l[DFFn*DM];
__device__ __nv_bfloat16 g_w2t_h[DM*DFFn],g_w2t_l[DM*DFFn];

// ================= converts =================
__device__ __forceinline__ void split_hilo(float v, __nv_bfloat16& h, __nv_bfloat16& l) {
    h = __float2bfloat16(v);
    l = __float2bfloat16(v - __bfloat162float(h));
}

__global__ void conv_hilo_kernel(const float* __restrict__ X,
                                 __nv_bfloat16* __restrict__ H, __nv_bfloat16* __restrict__ L,
                                 int n4) {
    int i = blockIdx.x * blockDim.x + threadIdx.x;
    if (i >= n4) return;
    float4 v = ((const float4*)X)[i];
    size_t o = (size_t)i * 4;
    split_hilo(v.x, H[o+0], L[o+0]);
    split_hilo(v.y, H[o+1], L[o+1]);
    split_hilo(v.z, H[o+2], L[o+2]);
    split_hilo(v.w, H[o+3], L[o+3]);
}

__global__ void concat_conv_kernel(const float* __restrict__ im, const float* __restrict__ doc,
                                   __nv_bfloat16* __restrict__ H, __nv_bfloat16* __restrict__ L) {
    int i = blockIdx.x * blockDim.x + threadIdx.x;
    const int total4 = Bb*LKt*(DM/4);
    if (i >= total4) return;
    int d4 = i % (DM/4); int bt = i / (DM/4);
    int b = bt / LKt, t = bt % LKt;
    const float* src = (t < LIMt) ? im + ((size_t)b*LIMt + t)*DM
                                  : doc + ((size_t)b*LQ + (t - LIMt))*DM;
    float4 v = *(const float4*)(src + d4*4);
    size_t o = (size_t)i * 4;
    split_hilo(v.x, H[o+0], L[o+0]);
    split_hilo(v.y, H[o+1], L[o+1]);
    split_hilo(v.z, H[o+2], L[o+2]);
    split_hilo(v.w, H[o+3], L[o+3]);
}

// W[K][N] row-major -> Th/Tl[N][K]
__global__ void wtrans_conv_kernel(const float* __restrict__ W,
                                   __nv_bfloat16* __restrict__ Th, __nv_bfloat16* __restrict__ Tl,
                                   int K, int N) {
    __shared__ float t[32][33];
    int n0 = blockIdx.x * 32, k0 = blockIdx.y * 32;
    int tx = threadIdx.x, ty = threadIdx.y;  // 32 x 8
    #pragma unroll
    for (int i = 0; i < 4; i++) {
        int k = ty + i*8;
        t[k][tx] = W[(size_t)(k0 + k)*N + n0 + tx];
    }
    __syncthreads();
    #pragma unroll
    for (int i = 0; i < 4; i++) {
        int n = ty + i*8;
        float v = t[tx][n];
        size_t o = (size_t)(n0 + n)*K + k0 + tx;
        __nv_bfloat16 h, l; split_hilo(v, h, l);
        Th[o] = h; Tl[o] = l;
    }
}

// ================= HMMA GEMM: C[M,N] = A[M,K] @ B[N,K]^T + bias =================
// 3-pass Markidis split: hi*hi + lo*hi + hi*lo, fp32 accumulators.
// CTA tile 128x128, 8 warps (2M x 4N), warp tile 64x32, K-chunk 64,
// cp.async double buffering. smem row stride 144B (conflict-free ldmatrix).
#define KT 64
#define ROWB 144                      // bytes per smem tile row
#define TILEB (128*ROWB)              // 18432 bytes per tile
#define GEMM_SMEM (4*TILEB)           // 73728

template<bool RELU, bool OUT_HILO>
__global__ void __launch_bounds__(256) gemm_tc_kernel(
    const __nv_bfloat16* __restrict__ Ah, const __nv_bfloat16* __restrict__ Al,
    const __nv_bfloat16* __restrict__ Bh, const __nv_bfloat16* __restrict__ Bl,
    const float* __restrict__ bias, float* __restrict__ C,
    __nv_bfloat16* __restrict__ OH, __nv_bfloat16* __restrict__ OL,
    int M, int N, int K)
{
    extern __shared__ char smem[];
    const uint32_t sbase = smem_to_u32(smem);
    const int tid = threadIdx.x, wid = tid >> 5, lane = tid & 31;
    const int wm = wid & 1, wn = wid >> 1;       // 2 x 4 warp grid
    const int m0 = blockIdx.y * 128, n0 = blockIdx.x * 128;

    const __nv_bfloat16* APs[3] = { Ah, Al, Ah };
    const __nv_bfloat16* BPs[3] = { Bh, Bh, Bl };
    const int KC = K / KT;
    const int NC = 3 * KC;

    float acc[4][4][4];
    #pragma unroll
    for (int i=0;i<4;i++)
        #pragma unroll
        for (int j=0;j<4;j++)
            #pragma unroll
            for (int r=0;r<4;r++) acc[i][j][r] = 0.f;

    // per-thread load coords: 1024 16B-chunks per tile, 4 per thread
    const int lr = tid >> 3;          // row granularity: 4 rows per iteration set
    const int lc = tid & 7;           // 8 chunks per row

    auto issue_chunk = [&](int c) {
        const int buf = c & 1;
        const int pass = c / KC;
        const int k0 = (c % KC) * KT;
        const __nv_bfloat16* Ap = APs[pass];
        const __nv_bfloat16* Bp = BPs[pass];
        uint32_t sA = sbase + buf * 2 * TILEB;
        uint32_t sB = sA + TILEB;
        #pragma unroll
        for (int it = 0; it < 4; it++) {
            int r = lr + it * 32;
            int gm = m0 + r;
            cp_async16(sA + r*ROWB + lc*16,
                       Ap + (size_t)gm * K + k0 + lc*8,
                       gm < M ? 16 : 0);
        }
        #pragma unroll
        for (int it = 0; it < 4; it++) {
            int r = lr + it * 32;
            cp_async16(sB + r*ROWB + lc*16,
                       Bp + (size_t)(n0 + r) * K + k0 + lc*8, 16);
        }
        cp_commit();
    };

    issue_chunk(0);
    for (int c = 0; c < NC; c++) {
        if (c + 1 < NC) { issue_chunk(c + 1); cp_wait<1>(); }
        else            { cp_wait<0>(); }
        __syncthreads();

        const int buf = c & 1;
        uint32_t sA = sbase + buf * 2 * TILEB;
        uint32_t sB = sA + TILEB;
        uint32_t aRowBase = sA + (wm*64 + (lane & 15)) * ROWB + (lane >> 4) * 16;
        uint32_t bRowBase = sB + (wn*32 + (lane & 15)) * ROWB + (lane >> 4) * 16;

        #pragma unroll
        for (int ks = 0; ks < 4; ks++) {
            const int kb = ks * 32;
            uint32_t bfr[4][2];
            #pragma unroll
            for (int np = 0; np < 2; np++) {
                uint32_t r0, r1, r2, r3;
                ldm_x4(r0, r1, r2, r3, bRowBase + np*16*ROWB + kb);
                bfr[np*2+0][0] = r0; bfr[np*2+0][1] = r2;
                bfr[np*2+1][0] = r1; bfr[np*2+1][1] = r3;
            }
            #pragma unroll
            for (int mt = 0; mt < 4; mt++) {
                uint32_t a0, a1, a2, a3;
                ldm_x4(a0, a1, a2, a3, aRowBase + mt*16*ROWB + kb);
                #pragma unroll
                for (int nt = 0; nt < 4; nt++)
                    mma16816(acc[mt][nt][0], acc[mt][nt][1], acc[mt][nt][2], acc[mt][nt][3],
                             a0, a1, a2, a3, bfr[nt][0], bfr[nt][1]);
            }
        }
        __syncthreads();
    }

    // epilogue: D frag layout: c0:(m=lane/4, n=(lane%4)*2), c1:n+1, c2:m+8, c3:m+8,n+1
    const int mr = lane >> 2, nc = (lane & 3) * 2;
    #pragma unroll
    for (int mt = 0; mt < 4; mt++) {
        #pragma unroll
        for (int half = 0; half < 2; half++) {
            int m = m0 + wm*64 + mt*16 + mr + half*8;
            if (m >= M) continue;
            #pragma unroll
            for (int nt = 0; nt < 4; nt++) {
                int n = n0 + wn*32 + nt*8 + nc;
                float v0 = acc[mt][nt][half*2+0] + bias[n];
                float v1 = acc[mt][nt][half*2+1] + bias[n+1];
                if (RELU) { v0 = fmaxf(v0, 0.f); v1 = fmaxf(v1, 0.f); }
                size_t o = (size_t)m * N + n;
                if (OUT_HILO) {
                    __nv_bfloat16 h0,l0,h1,l1;
                    split_hilo(v0,h0,l0); split_hilo(v1,h1,l1);
                    OH[o] = h0; OH[o+1] = h1; OL[o] = l0; OL[o+1] = l1;
                } else {
                    C[o] = v0; C[o+1] = v1;
                }
            }
        }
    }
}

// ================= flash attention with relative-position bias (SIMT fp32) =================
struct AttnSmem {
    float Qs[64][65];
    float Ks[64][65];
    float Vs[64][65];
    float Ps[64][65];
    float red1[64][8];
    float red2[64][8];
    float bx[201];
    float by[201];
    int qx[64], qy[64], kx[64], ky[64];
};

__global__ void __launch_bounds__(128) attn_kernel(
    const float* __restrict__ qb, const float* __restrict__ kb_, const float* __restrict__ vb_,
    const int* __restrict__ dqx, const int* __restrict__ dqy,
    const int* __restrict__ imx, const int* __restrict__ imy,
    const float* __restrict__ bias_x, const float* __restrict__ bias_y,
    __nv_bfloat16* __restrict__ ctxH, __nv_bfloat16* __restrict__ ctxL)
{
    extern __shared__ char smem_raw[];
    AttnSmem& S = *reinterpret_cast<AttnSmem*>(smem_raw);
    const int tid = threadIdx.x;
    const int ty = tid >> 3, tx = tid & 7;
    const int qt = blockIdx.x;
    const int bh = blockIdx.y;
    const int b = bh / NH, h = bh % NH;
    const int qbase = qt * 64;
    const int r0 = ty * 4;
    const int c0 = tx * 8;

    for (int e = tid; e < 64*64; e += 128) {
        int r = e >> 6, d = e & 63;
        S.Qs[r][d] = qb[(size_t)(b*LQ + qbase + r)*DM + h*DKh + d];
    }
    for (int i = tid; i < 201; i += 128) {
        S.bx[i] = bias_x[i*NH + h];
        S.by[i] = bias_y[i*NH + h];
    }
    if (tid < 64) {
        S.qx[tid] = dqx[b*LQ + qbase + tid];
        S.qy[tid] = dqy[b*LQ + qbase + tid];
    }

    float o[4][8];
    #pragma unroll
    for (int i=0;i<4;i++)
        #pragma unroll
        for (int j=0;j<8;j++) o[i][j]=0.f;
    float mreg[4], lreg[4];
    #pragma unroll
    for (int i=0;i<4;i++){ mreg[i] = -1e30f; lreg[i] = 0.f; }

    const int NT = (LKt + 63) / 64;
    for (int kt = 0; kt < NT; kt++) {
        const int kbase = kt * 64;
        __syncthreads();
        for (int e = tid; e < 64*64; e += 128) {
            int r = e >> 6, d = e & 63;
            int kg = kbase + r;
            float kk = 0.f, vv = 0.f;
            if (kg < LKt) {
                size_t off = (size_t)(b*LKt + kg)*DM + h*DKh + d;
                kk = kb_[off];
                vv = vb_[off];
            }
            S.Ks[r][d] = kk;
            S.Vs[r][d] = vv;
        }
        if (tid < 64) {
            int kg = kbase + tid;
            int xv = 0, yv = 0;
            if (kg < LKt) {
                if (kg < LIMt) { xv = imx[b*LIMt + kg];        yv = imy[b*LIMt + kg]; }
                else           { xv = dqx[b*LQ + kg - LIMt];   yv = dqy[b*LQ + kg - LIMt]; }
            }
            S.kx[tid] = xv; S.ky[tid] = yv;
        }
        __syncthreads();

        float s[4][8];
        #pragma unroll
        for (int i=0;i<4;i++)
            #pragma unroll
            for (int j=0;j<8;j++) s[i][j]=0.f;
        #pragma unroll 4
        for (int d=0; d<64; d++) {
            float qa[4], kreg[8];
            #pragma unroll
            for (int i=0;i<4;i++) qa[i] = S.Qs[r0+i][d];
            #pragma unroll
            for (int j=0;j<8;j++) kreg[j] = S.Ks[c0+j][d];
            #pragma unroll
            for (int i=0;i<4;i++)
                #pragma unroll
                for (int j=0;j<8;j++) s[i][j] = fmaf(qa[i], kreg[j], s[i][j]);
        }
        #pragma unroll
        for (int i=0;i<4;i++) {
            int qxv = S.qx[r0+i], qyv = S.qy[r0+i];
            #pragma unroll
            for (int j=0;j<8;j++) {
                int c = c0 + j;
                int rx = qxv - S.kx[c]; rx = rx < -MD ? -MD : (rx > MD ? MD : rx);
                int ry = qyv - S.ky[c]; ry = ry < -MD ? -MD : (ry > MD ? MD : ry);
                float val = s[i][j]*0.125f + S.bx[rx + MD] + S.by[ry + MD];
                if (kbase + c >= LKt) val = -1e30f;
                s[i][j] = val;
            }
        }
        #pragma unroll
        for (int i=0;i<4;i++) {
            float tm = s[i][0];
            #pragma unroll
            for (int j=1;j<8;j++) tm = fmaxf(tm, s[i][j]);
            S.red1[r0+i][tx] = tm;
        }
        __syncthreads();
        float factor[4];
        #pragma unroll
        for (int i=0;i<4;i++) {
            float nm = mreg[i];
            #pragma unroll
            for (int t=0;t<8;t++) nm = fmaxf(nm, S.red1[r0+i][t]);
            factor[i] = __expf(mreg[i] - nm);
            mreg[i] = nm;
        }
        #pragma unroll
        for (int i=0;i<4;i++) {
            float rs = 0.f;
            #pragma unroll
            for (int j=0;j<8;j++) {
                float p = __expf(s[i][j] - mreg[i]);
                S.Ps[r0+i][c0+j] = p;
                rs += p;
            }
            S.red2[r0+i][tx] = rs;
            #pragma unroll
            for (int j=0;j<8;j++) o[i][j] *= factor[i];
        }
        __syncthreads();
        #pragma unroll
        for (int i=0;i<4;i++) {
            float rs = 0.f;
            #pragma unroll
            for (int t=0;t<8;t++) rs += S.red2[r0+i][t];
            lreg[i] = lreg[i]*factor[i] + rs;
        }
        #pragma unroll 4
        for (int k=0;k<64;k++) {
            float pa[4], vr[8];
            #pragma unroll
            for (int i=0;i<4;i++) pa[i] = S.Ps[r0+i][k];
            #pragma unroll
            for (int j=0;j<8;j++) vr[j] = S.Vs[k][c0+j];
            #pragma unroll
            for (int i=0;i<4;i++)
                #pragma unroll
                for (int j=0;j<8;j++) o[i][j] = fmaf(pa[i], vr[j], o[i][j]);
        }
    }
    #pragma unroll
    for (int i=0;i<4;i++) {
        float inv = 1.f / lreg[i];
        #pragma unroll
        for (int j=0;j<8;j++) {
            float v = o[i][j]*inv;
            size_t off = (size_t)(b*LQ + qbase + r0 + i)*DM + h*DKh + c0 + j;
            __nv_bfloat16 hh, ll; split_hilo(v, hh, ll);
            ctxH[off] = hh; ctxL[off] = ll;
        }
    }
}

// ================= fused add + LayerNorm =================
template<bool HILO>
__global__ void __launch_bounds__(256) addln_kernel(
    const float* __restrict__ A, const float* __restrict__ Cv,
    const float* __restrict__ g, const float* __restrict__ be,
    float* __restrict__ out, __nv_bfloat16* __restrict__ OH, __nv_bfloat16* __restrict__ OL)
{
    __shared__ float sred[256];
    const int row = blockIdx.x;
    const int tid = threadIdx.x;
    const size_t base = (size_t)row * DM;

    float x[3];
    #pragma unroll
    for (int i=0;i<3;i++) {
        int col = tid + 256*i;
        x[i] = A[base + col] + Cv[base + col];
    }
    float s = x[0] + x[1] + x[2];
    sred[tid] = s; __syncthreads();
    for (int off=128; off>0; off>>=1) {
        if (tid < off) sred[tid] += sred[tid+off];
        __syncthreads();
    }
    float mu = sred[0] * (1.f/DM);
    __syncthreads();
    float d0=x[0]-mu, d1=x[1]-mu, d2=x[2]-mu;
    sred[tid] = d0*d0 + d1*d1 + d2*d2; __syncthreads();
    for (int off=128; off>0; off>>=1) {
        if (tid < off) sred[tid] += sred[tid+off];
        __syncthreads();
    }
    float rs = rsqrtf(sred[0] * (1.f/DM) + 1e-5f);
    #pragma unroll
    for (int i=0;i<3;i++) {
        int col = tid + 256*i;
        float v = (x[i] - mu) * rs * g[col] + be[col];
        out[base + col] = v;
        if (HILO) {
            __nv_bfloat16 h, l; split_hilo(v, h, l);
            OH[base + col] = h; OL[base + col] = l;
        }
    }
}

// ================= launch =================
extern "C" void kernel_launch(void* const* d_in, const int* in_sizes, int n_in,
                              void* d_out, int out_size) {
    const float* docqa  = (const float*)d_in[0];
    const float* im     = (const float*)d_in[1];
    const int*   dqx    = (const int*)  d_in[2];
    const int*   dqy    = (const int*)  d_in[3];
    const int*   imx    = (const int*)  d_in[4];
    const int*   imy    = (const int*)  d_in[5];
    const float* Wq     = (const float*)d_in[6];
    const float* bq     = (const float*)d_in[7];
    const float* Wk     = (const float*)d_in[8];
    const float* bk     = (const float*)d_in[9];
    const float* Wv     = (const float*)d_in[10];
    const float* bv     = (const float*)d_in[11];
    const float* Wo     = (const float*)d_in[12];
    const float* bo     = (const float*)d_in[13];
    const float* bias_x = (const float*)d_in[14];
    const float* bias_y = (const float*)d_in[15];
    const float* W1     = (const float*)d_in[16];
    const float* b1     = (const float*)d_in[17];
    const float* W2     = (const float*)d_in[18];
    const float* b2     = (const float*)d_in[19];
    const float* g1     = (const float*)d_in[20];
    const float* be1    = (const float*)d_in[21];
    const float* g2     = (const float*)d_in[22];
    const float* be2    = (const float*)d_in[23];
    float* out = (float*)d_out;

    float *p_q, *p_k, *p_v, *p_tmp, *p_src1;
    cudaGetSymbolAddress((void**)&p_q,    g_q);
    cudaGetSymbolAddress((void**)&p_k,    g_k);
    cudaGetSymbolAddress((void**)&p_v,    g_v);
    cudaGetSymbolAddress((void**)&p_tmp,  g_tmp);
    cudaGetSymbolAddress((void**)&p_src1, g_src1);

    __nv_bfloat16 *full_h,*full_l,*dq_h,*dq_l,*ctx_h,*ctx_l,*s1_h,*s1_l,*f1_h,*f1_l;
    __nv_bfloat16 *wqt_h,*wqt_l,*wkt_h,*wkt_l,*wvt_h,*wvt_l,*wot_h,*wot_l,*w1t_h,*w1t_l,*w2t_h,*w2t_l;
    cudaGetSymbolAddress((void**)&full_h, g_full_h); cudaGetSymbolAddress((void**)&full_l, g_full_l);
    cudaGetSymbolAddress((void**)&dq_h,   g_dq_h);   cudaGetSymbolAddress((void**)&dq_l,   g_dq_l);
    cudaGetSymbolAddress((void**)&ctx_h,  g_ctx_h);  cudaGetSymbolAddress((void**)&ctx_l,  g_ctx_l);
    cudaGetSymbolAddress((void**)&s1_h,   g_s1_h);   cudaGetSymbolAddress((void**)&s1_l,   g_s1_l);
    cudaGetSymbolAddress((void**)&f1_h,   g_f1_h);   cudaGetSymbolAddress((void**)&f1_l,   g_f1_l);
    cudaGetSymbolAddress((void**)&wqt_h,  g_wqt_h);  cudaGetSymbolAddress((void**)&wqt_l,  g_wqt_l);
    cudaGetSymbolAddress((void**)&wkt_h,  g_wkt_h);  cudaGetSymbolAddress((void**)&wkt_l,  g_wkt_l);
    cudaGetSymbolAddress((void**)&wvt_h,  g_wvt_h);  cudaGetSymbolAddress((void**)&wvt_l,  g_wvt_l);
    cudaGetSymbolAddress((void**)&wot_h,  g_wot_h);  cudaGetSymbolAddress((void**)&wot_l,  g_wot_l);
    cudaGetSymbolAddress((void**)&w1t_h,  g_w1t_h);  cudaGetSymbolAddress((void**)&w1t_l,  g_w1t_l);
    cudaGetSymbolAddress((void**)&w2t_h,  g_w2t_h);  cudaGetSymbolAddress((void**)&w2t_l,  g_w2t_l);

    cudaFuncSetAttribute(gemm_tc_kernel<false,false>, cudaFuncAttributeMaxDynamicSharedMemorySize, GEMM_SMEM);
    cudaFuncSetAttribute(gemm_tc_kernel<true, true >, cudaFuncAttributeMaxDynamicSharedMemorySize, GEMM_SMEM);
    cudaFuncSetAttribute(attn_kernel, cudaFuncAttributeMaxDynamicSharedMemorySize, (int)sizeof(AttnSmem));

    const int MQ = Bb*LQ;     // 2560
    const int MK = Bb*LKt;    // 7744

    // --- converts ---
    {
        int t4 = Bb*LKt*(DM/4);
        concat_conv_kernel<<<(t4+255)/256, 256>>>(im, docqa, full_h, full_l);
        int q4 = Bb*LQ*(DM/4);
        conv_hilo_kernel<<<(q4+255)/256, 256>>>(docqa, dq_h, dq_l, q4);
        dim3 tb(32,8);
        wtrans_conv_kernel<<<dim3(DM/32,   DM/32),   tb>>>(Wq, wqt_h, wqt_l, DM,   DM);
        wtrans_conv_kernel<<<dim3(DM/32,   DM/32),   tb>>>(Wk, wkt_h, wkt_l, DM,   DM);
        wtrans_conv_kernel<<<dim3(DM/32,   DM/32),   tb>>>(Wv, wvt_h, wvt_l, DM,   DM);
        wtrans_conv_kernel<<<dim3(DM/32,   DM/32),   tb>>>(Wo, wot_h, wot_l, DM,   DM);
        wtrans_conv_kernel<<<dim3(DFFn/32, DM/32),   tb>>>(W1, w1t_h, w1t_l, DM,   DFFn);
        wtrans_conv_kernel<<<dim3(DM/32,   DFFn/32), tb>>>(W2, w2t_h, w2t_l, DFFn, DM);
    }

    // --- projections (HMMA) ---
    gemm_tc_kernel<false,false><<<dim3(DM/128, (MQ+127)/128), 256, GEMM_SMEM>>>(
        dq_h, dq_l, wqt_h, wqt_l, bq, p_q, nullptr, nullptr, MQ, DM, DM);
    gemm_tc_kernel<false,false><<<dim3(DM/128, (MK+127)/128), 256, GEMM_SMEM>>>(
        full_h, full_l, wkt_h, wkt_l, bk, p_k, nullptr, nullptr, MK, DM, DM);
    gemm_tc_kernel<false,false><<<dim3(DM/128, (MK+127)/128), 256, GEMM_SMEM>>>(
        full_h, full_l, wvt_h, wvt_l, bv, p_v, nullptr, nullptr, MK, DM, DM);

    // --- attention ---
    attn_kernel<<<dim3(LQ/64, Bb*NH), 128, sizeof(AttnSmem)>>>(
        p_q, p_k, p_v, dqx, dqy, imx, imy, bias_x, bias_y, ctx_h, ctx_l);

    // --- output proj + LN + FFN + LN ---
    gemm_tc_kernel<false,false><<<dim3(DM/128, (MQ+127)/128), 256, GEMM_SMEM>>>(
        ctx_h, ctx_l, wot_h, wot_l, bo, p_tmp, nullptr, nullptr, MQ, DM, DM);
    addln_kernel<true><<<MQ, 256>>>(docqa, p_tmp, g1, be1, p_src1, s1_h, s1_l);
    gemm_tc_kernel<true,true><<<dim3(DFFn/128, (MQ+127)/128), 256, GEMM_SMEM>>>(
        s1_h, s1_l, w1t_h, w1t_l, b1, nullptr, f1_h, f1_l, MQ, DFFn, DM);
    gemm_tc_kernel<false,false><<<dim3(DM/128, (MQ+127)/128), 256, GEMM_SMEM>>>(
        f1_h, f1_l, w2t_h, w2t_l, b2, p_tmp, nullptr, nullptr, MQ, DM, DFFn);
    addln_kernel<false><<<MQ, 256>>>(p_src1, p_tmp, g2, be2, out, nullptr, nullptr);
}

// round 5
// speedup vs baseline: 2.2892x; 1.5854x over previous
#include <cuda_runtime.h>
#include <cuda_bf16.h>
#include <math.h>
#include <stdint.h>

#define Bb 4
#define LQ 640
#define LIMt 1296
#define LKt 1936
#define DM 768
#define NH 12
#define DKh 64
#define DFFn 3072
#define MD 100

// ================= helpers =================
__device__ __forceinline__ uint32_t smem_to_u32(const void* p) {
    uint32_t a;
    asm("{ .reg .u64 t; cvta.to.shared.u64 t, %1; cvt.u32.u64 %0, t; }" : "=r"(a) : "l"(p));
    return a;
}
__device__ __forceinline__ void cp_async16(uint32_t dst, const void* src, int src_bytes) {
    asm volatile("cp.async.cg.shared.global [%0], [%1], 16, %2;"
                 :: "r"(dst), "l"(src), "r"(src_bytes) : "memory");
}
__device__ __forceinline__ void cp_async4(uint32_t dst, const void* src, int src_bytes) {
    asm volatile("cp.async.ca.shared.global [%0], [%1], 4, %2;"
                 :: "r"(dst), "l"(src), "r"(src_bytes) : "memory");
}
__device__ __forceinline__ void cp_commit() {
    asm volatile("cp.async.commit_group;" ::: "memory");
}
template<int N>
__device__ __forceinline__ void cp_wait() {
    asm volatile("cp.async.wait_group %0;" :: "n"(N) : "memory");
}
__device__ __forceinline__ void ldm_x4(uint32_t& r0, uint32_t& r1, uint32_t& r2, uint32_t& r3,
                                       uint32_t addr) {
    asm volatile("ldmatrix.sync.aligned.m8n8.x4.shared.b16 {%0,%1,%2,%3}, [%4];"
                 : "=r"(r0), "=r"(r1), "=r"(r2), "=r"(r3) : "r"(addr));
}
__device__ __forceinline__ void ldm_x4t(uint32_t& r0, uint32_t& r1, uint32_t& r2, uint32_t& r3,
                                        uint32_t addr) {
    asm volatile("ldmatrix.sync.aligned.m8n8.x4.trans.shared.b16 {%0,%1,%2,%3}, [%4];"
                 : "=r"(r0), "=r"(r1), "=r"(r2), "=r"(r3) : "r"(addr));
}
__device__ __forceinline__ void mma16816(float& d0, float& d1, float& d2, float& d3,
                                         uint32_t a0, uint32_t a1, uint32_t a2, uint32_t a3,
                                         uint32_t b0, uint32_t b1) {
    asm volatile("mma.sync.aligned.m16n8k16.row.col.f32.bf16.bf16.f32 "
                 "{%0,%1,%2,%3}, {%4,%5,%6,%7}, {%8,%9}, {%0,%1,%2,%3};"
                 : "+f"(d0), "+f"(d1), "+f"(d2), "+f"(d3)
                 : "r"(a0), "r"(a1), "r"(a2), "r"(a3), "r"(b0), "r"(b1));
}
// pack two f32 -> bf16x2 reg {lo, hi}
__device__ __forceinline__ uint32_t pack_bf16x2(float lo, float hi) {
    uint32_t r;
    asm("cvt.rn.bf16x2.f32 %0, %1, %2;" : "=r"(r) : "f"(hi), "f"(lo));
    return r;
}
// fast exp2 on FMA pipe; valid for a <= ~1, clamps below -126 -> ~0
__device__ __forceinline__ float exp2_poly(float a) {
    a = fmaxf(a, -126.f);
    float z = a + 12582912.f;
    int ir = __float_as_int(z) - 0x4B400000;
    float r = z - 12582912.f;
    float f = a - r;
    float p = 0.0096181291f;
    p = fmaf(p, f, 0.0555041087f);
    p = fmaf(p, f, 0.2402265070f);
    p = fmaf(p, f, 0.6931471806f);
    p = fmaf(p, f, 1.0f);
    return p * __int_as_float((ir + 127) << 23);
}

// ================= scratch =================
__device__ float g_tmp [Bb*LQ*DM];
__device__ float g_src1[Bb*LQ*DM];

__device__ __nv_bfloat16 g_full_h[Bb*LKt*DM], g_full_l[Bb*LKt*DM];
__device__ __nv_bfloat16 g_dq_h  [Bb*LQ*DM],  g_dq_l  [Bb*LQ*DM];
__device__ __nv_bfloat16 g_qh [Bb*LQ*DM],  g_ql [Bb*LQ*DM];
__device__ __nv_bfloat16 g_kh [Bb*LKt*DM], g_kl [Bb*LKt*DM];
__device__ __nv_bfloat16 g_vh [Bb*LKt*DM], g_vl [Bb*LKt*DM];
__device__ __nv_bfloat16 g_ctx_h [Bb*LQ*DM],  g_ctx_l [Bb*LQ*DM];
__device__ __nv_bfloat16 g_s1_h  [Bb*LQ*DM],  g_s1_l  [Bb*LQ*DM];
__device__ __nv_bfloat16 g_f1_h  [Bb*LQ*DFFn],g_f1_l  [Bb*LQ*DFFn];
__device__ __nv_bfloat16 g_wqt_h[DM*DM],  g_wqt_l[DM*DM];
__device__ __nv_bfloat16 g_wkt_h[DM*DM],  g_wkt_l[DM*DM];
__device__ __nv_bfloat16 g_wvt_h[DM*DM],  g_wvt_l[DM*DM];
__device__ __nv_bfloat16 g_wot_h[DM*DM],  g_wot_l[DM*DM];
__device__ __nv_bfloat16 g_w1t_h[DFFn*DM],g_w1t_l[DFFn*DM];
__device__ __nv_bfloat16 g_w2t_h[DM*DFFn],g_w2t_l[DM*DFFn];

// ================= converts =================
__device__ __forceinline__ void split_hilo(float v, __nv_bfloat16& h, __nv_bfloat16& l) {
    h = __float2bfloat16(v);
    l = __float2bfloat16(v - __bfloat162float(h));
}

__global__ void conv_hilo_kernel(const float* __restrict__ X,
                                 __nv_bfloat16* __restrict__ H, __nv_bfloat16* __restrict__ L,
                                 int n4) {
    int i = blockIdx.x * blockDim.x + threadIdx.x;
    if (i >= n4) return;
    float4 v = ((const float4*)X)[i];
    size_t o = (size_t)i * 4;
    split_hilo(v.x, H[o+0], L[o+0]);
    split_hilo(v.y, H[o+1], L[o+1]);
    split_hilo(v.z, H[o+2], L[o+2]);
    split_hilo(v.w, H[o+3], L[o+3]);
}

__global__ void concat_conv_kernel(const float* __restrict__ im, const float* __restrict__ doc,
                                   __nv_bfloat16* __restrict__ H, __nv_bfloat16* __restrict__ L) {
    int i = blockIdx.x * blockDim.x + threadIdx.x;
    const int total4 = Bb*LKt*(DM/4);
    if (i >= total4) return;
    int d4 = i % (DM/4); int bt = i / (DM/4);
    int b = bt / LKt, t = bt % LKt;
    const float* src = (t < LIMt) ? im + ((size_t)b*LIMt + t)*DM
                                  : doc + ((size_t)b*LQ + (t - LIMt))*DM;
    float4 v = *(const float4*)(src + d4*4);
    size_t o = (size_t)i * 4;
    split_hilo(v.x, H[o+0], L[o+0]);
    split_hilo(v.y, H[o+1], L[o+1]);
    split_hilo(v.z, H[o+2], L[o+2]);
    split_hilo(v.w, H[o+3], L[o+3]);
}

__global__ void wtrans_conv_kernel(const float* __restrict__ W,
                                   __nv_bfloat16* __restrict__ Th, __nv_bfloat16* __restrict__ Tl,
                                   int K, int N) {
    __shared__ float t[32][33];
    int n0 = blockIdx.x * 32, k0 = blockIdx.y * 32;
    int tx = threadIdx.x, ty = threadIdx.y;  // 32 x 8
    #pragma unroll
    for (int i = 0; i < 4; i++) {
        int k = ty + i*8;
        t[k][tx] = W[(size_t)(k0 + k)*N + n0 + tx];
    }
    __syncthreads();
    #pragma unroll
    for (int i = 0; i < 4; i++) {
        int n = ty + i*8;
        float v = t[tx][n];
        size_t o = (size_t)(n0 + n)*K + k0 + tx;
        __nv_bfloat16 h, l; split_hilo(v, h, l);
        Th[o] = h; Tl[o] = l;
    }
}

// ================= HMMA GEMM (unchanged from round 4, + hilo-out variant) =================
#define KT 64
#define ROWB 144
#define TILEB (128*ROWB)
#define GEMM_SMEM (4*TILEB)

template<bool RELU, bool OUT_HILO>
__global__ void __launch_bounds__(256) gemm_tc_kernel(
    const __nv_bfloat16* __restrict__ Ah, const __nv_bfloat16* __restrict__ Al,
    const __nv_bfloat16* __restrict__ Bh, const __nv_bfloat16* __restrict__ Bl,
    const float* __restrict__ bias, float* __restrict__ C,
    __nv_bfloat16* __restrict__ OH, __nv_bfloat16* __restrict__ OL,
    int M, int N, int K)
{
    extern __shared__ char smem[];
    const uint32_t sbase = smem_to_u32(smem);
    const int tid = threadIdx.x, wid = tid >> 5, lane = tid & 31;
    const int wm = wid & 1, wn = wid >> 1;
    const int m0 = blockIdx.y * 128, n0 = blockIdx.x * 128;

    const __nv_bfloat16* APs[3] = { Ah, Al, Ah };
    const __nv_bfloat16* BPs[3] = { Bh, Bh, Bl };
    const int KC = K / KT;
    const int NC = 3 * KC;

    float acc[4][4][4];
    #pragma unroll
    for (int i=0;i<4;i++)
        #pragma unroll
        for (int j=0;j<4;j++)
            #pragma unroll
            for (int r=0;r<4;r++) acc[i][j][r] = 0.f;

    const int lr = tid >> 3;
    const int lc = tid & 7;

    auto issue_chunk = [&](int c) {
        const int buf = c & 1;
        const int pass = c / KC;
        const int k0 = (c % KC) * KT;
        const __nv_bfloat16* Ap = APs[pass];
        const __nv_bfloat16* Bp = BPs[pass];
        uint32_t sA = sbase + buf * 2 * TILEB;
        uint32_t sB = sA + TILEB;
        #pragma unroll
        for (int it = 0; it < 4; it++) {
            int r = lr + it * 32;
            int gm = m0 + r;
            cp_async16(sA + r*ROWB + lc*16,
                       Ap + (size_t)gm * K + k0 + lc*8,
                       gm < M ? 16 : 0);
        }
        #pragma unroll
        for (int it = 0; it < 4; it++) {
            int r = lr + it * 32;
            cp_async16(sB + r*ROWB + lc*16,
                       Bp + (size_t)(n0 + r) * K + k0 + lc*8, 16);
        }
        cp_commit();
    };

    issue_chunk(0);
    for (int c = 0; c < NC; c++) {
        if (c + 1 < NC) { issue_chunk(c + 1); cp_wait<1>(); }
        else            { cp_wait<0>(); }
        __syncthreads();

        const int buf = c & 1;
        uint32_t sA = sbase + buf * 2 * TILEB;
        uint32_t sB = sA + TILEB;
        uint32_t aRowBase = sA + (wm*64 + (lane & 15)) * ROWB + (lane >> 4) * 16;
        uint32_t bRowBase = sB + (wn*32 + (lane & 15)) * ROWB + (lane >> 4) * 16;

        #pragma unroll
        for (int ks = 0; ks < 4; ks++) {
            const int kb = ks * 32;
            uint32_t bfr[4][2];
            #pragma unroll
            for (int np = 0; np < 2; np++) {
                uint32_t r0, r1, r2, r3;
                ldm_x4(r0, r1, r2, r3, bRowBase + np*16*ROWB + kb);
                bfr[np*2+0][0] = r0; bfr[np*2+0][1] = r2;
                bfr[np*2+1][0] = r1; bfr[np*2+1][1] = r3;
            }
            #pragma unroll
            for (int mt = 0; mt < 4; mt++) {
                uint32_t a0, a1, a2, a3;
                ldm_x4(a0, a1, a2, a3, aRowBase + mt*16*ROWB + kb);
                #pragma unroll
                for (int nt = 0; nt < 4; nt++)
                    mma16816(acc[mt][nt][0], acc[mt][nt][1], acc[mt][nt][2], acc[mt][nt][3],
                             a0, a1, a2, a3, bfr[nt][0], bfr[nt][1]);
            }
        }
        __syncthreads();
    }

    const int mr = lane >> 2, nc = (lane & 3) * 2;
    #pragma unroll
    for (int mt = 0; mt < 4; mt++) {
        #pragma unroll
        for (int half = 0; half < 2; half++) {
            int m = m0 + wm*64 + mt*16 + mr + half*8;
            if (m >= M) continue;
            #pragma unroll
            for (int nt = 0; nt < 4; nt++) {
                int n = n0 + wn*32 + nt*8 + nc;
                float v0 = acc[mt][nt][half*2+0] + bias[n];
                float v1 = acc[mt][nt][half*2+1] + bias[n+1];
                if (RELU) { v0 = fmaxf(v0, 0.f); v1 = fmaxf(v1, 0.f); }
                size_t o = (size_t)m * N + n;
                if (OUT_HILO) {
                    __nv_bfloat16 h0,l0,h1,l1;
                    split_hilo(v0,h0,l0); split_hilo(v1,h1,l1);
                    OH[o] = h0; OH[o+1] = h1; OL[o] = l0; OL[o+1] = l1;
                } else {
                    C[o] = v0; C[o+1] = v1;
                }
            }
        }
    }
}

// ================= HMMA flash attention with relative-position bias =================
#define ATS 72           // smem tile stride in halves (144 B)
#define ATSB 144
#define QTILE_BYTES (64*ATSB)

struct AttnSmem2 {
    __nv_bfloat16 Qh[64*ATS], Ql[64*ATS];
    __nv_bfloat16 Kh[2][64*ATS], Kl[2][64*ATS], Vh[2][64*ATS], Vl[2][64*ATS];
    float bx[201], by[201];
    int qx[64], qy[64];
    int kx[2][64], ky[2][64];
};

#define CSC 0.18033688011116f   /* 0.125 * log2(e) */

__global__ void __launch_bounds__(128) attn_kernel(
    const __nv_bfloat16* __restrict__ qhg, const __nv_bfloat16* __restrict__ qlg,
    const __nv_bfloat16* __restrict__ khg, const __nv_bfloat16* __restrict__ klg,
    const __nv_bfloat16* __restrict__ vhg, const __nv_bfloat16* __restrict__ vlg,
    const int* __restrict__ dqx, const int* __restrict__ dqy,
    const int* __restrict__ imx, const int* __restrict__ imy,
    const float* __restrict__ bias_x, const float* __restrict__ bias_y,
    __nv_bfloat16* __restrict__ ctxH, __nv_bfloat16* __restrict__ ctxL)
{
    extern __shared__ char smem_raw[];
    AttnSmem2& S = *reinterpret_cast<AttnSmem2*>(smem_raw);
    const int tid = threadIdx.x;
    const int lane = tid & 31, w = tid >> 5;
    const int qt = blockIdx.x;
    const int bh = blockIdx.y;
    const int b = bh / NH, h = bh % NH;
    const int qbase = qt * 64;
    const int bLK = b * LKt;
    const int hd = h * DKh;

    const uint32_t sQh = smem_to_u32(S.Qh), sQl = smem_to_u32(S.Ql);
    uint32_t sKh[2] = { smem_to_u32(S.Kh[0]), smem_to_u32(S.Kh[1]) };
    uint32_t sKl[2] = { smem_to_u32(S.Kl[0]), smem_to_u32(S.Kl[1]) };
    uint32_t sVh[2] = { smem_to_u32(S.Vh[0]), smem_to_u32(S.Vh[1]) };
    uint32_t sVl[2] = { smem_to_u32(S.Vl[0]), smem_to_u32(S.Vl[1]) };
    uint32_t sKx[2] = { smem_to_u32(S.kx[0]), smem_to_u32(S.kx[1]) };
    uint32_t sKy[2] = { smem_to_u32(S.ky[0]), smem_to_u32(S.ky[1]) };

    // ---- load Q tiles + bias tables + q coords (plain) ----
    #pragma unroll
    for (int it = 0; it < 4; it++) {
        int ch = tid + it*128;
        int row = ch >> 3, off = (ch & 7) * 8;
        size_t g = (size_t)(b*LQ + qbase + row)*DM + hd + off;
        *(float4*)((char*)S.Qh + row*ATSB + off*2) = *(const float4*)(qhg + g);
        *(float4*)((char*)S.Ql + row*ATSB + off*2) = *(const float4*)(qlg + g);
    }
    const float LOG2E = 1.4426950408889634f;
    for (int i = tid; i < 201; i += 128) {
        S.bx[i] = bias_x[i*NH + h] * LOG2E;
        S.by[i] = bias_y[i*NH + h] * LOG2E;
    }
    if (tid < 64) S.qx[tid] = dqx[b*LQ + qbase + tid];
    else if (tid < 128) S.qy[tid-64] = dqy[b*LQ + qbase + (tid-64)];

    // ---- K/V prefetch machinery ----
    auto issue_kv = [&](int kt) {
        const int buf = kt & 1;
        const int kbase = kt * 64;
        #pragma unroll
        for (int it = 0; it < 4; it++) {
            int ch = tid + it*128;
            int row = ch >> 3, off = (ch & 7) * 8;
            int kg = kbase + row;
            int nb = kg < LKt ? 16 : 0;
            size_t g = (size_t)(bLK + kg)*DM + hd + off;
            uint32_t so = row*ATSB + off*2;
            cp_async16(sKh[buf] + so, khg + g, nb);
            cp_async16(sKl[buf] + so, klg + g, nb);
            cp_async16(sVh[buf] + so, vhg + g, nb);
            cp_async16(sVl[buf] + so, vlg + g, nb);
        }
        {
            int j = tid & 63;
            int kg = kbase + j;
            const int* src;
            if (tid < 64) src = (kg < LIMt) ? (imx + b*LIMt + kg) : (dqx + b*LQ + (kg - LIMt));
            else          src = (kg < LIMt) ? (imy + b*LIMt + kg) : (dqy + b*LQ + (kg - LIMt));
            uint32_t dst = (tid < 64 ? sKx[buf] : sKy[buf]) + j*4;
            cp_async4(dst, src, kg < LKt ? 4 : 0);
        }
        cp_commit();
    };

    issue_kv(0);
    __syncthreads();

    // ---- Q fragments (persistent) ----
    uint32_t qa_h[4][4], qa_l[4][4];
    {
        uint32_t aBase = (w*16 + (lane & 15))*ATSB + (lane >> 4)*16;
        #pragma unroll
        for (int s = 0; s < 4; s++) {
            ldm_x4(qa_h[s][0], qa_h[s][1], qa_h[s][2], qa_h[s][3], sQh + aBase + s*32);
            ldm_x4(qa_l[s][0], qa_l[s][1], qa_l[s][2], qa_l[s][3], sQl + aBase + s*32);
        }
    }

    const int r1 = w*16 + (lane >> 2);       // local q row for c0/c1 (r2 = r1+8)
    float oacc[8][4];
    #pragma unroll
    for (int d=0; d<8; d++)
        #pragma unroll
        for (int r=0; r<4; r++) oacc[d][r] = 0.f;
    float m1 = -1e30f, m2 = -1e30f, l1 = 0.f, l2 = 0.f;

    const int NT = (LKt + 63) / 64;  // 31
    for (int kt = 0; kt < NT; kt++) {
        if (kt > 0) __syncthreads();
        if (kt + 1 < NT) { issue_kv(kt + 1); cp_wait<1>(); }
        else             { cp_wait<0>(); }
        __syncthreads();

        const int buf = kt & 1;
        const int kbase = kt * 64;

        // ---- S = Q K^T (3 passes) ----
        float sc[8][4];
        #pragma unroll
        for (int nt=0; nt<8; nt++)
            #pragma unroll
            for (int r=0; r<4; r++) sc[nt][r] = 0.f;

        uint32_t bBase = (lane & 15)*ATSB + (lane >> 4)*16;
        #pragma unroll
        for (int s = 0; s < 4; s++) {
            uint32_t bf[8][2];
            #pragma unroll
            for (int np = 0; np < 4; np++) {
                uint32_t r0, r1_, r2_, r3_;
                ldm_x4(r0, r1_, r2_, r3_, sKh[buf] + bBase + np*16*ATSB + s*32);
                bf[np*2+0][0] = r0;  bf[np*2+0][1] = r2_;
                bf[np*2+1][0] = r1_; bf[np*2+1][1] = r3_;
            }
            #pragma unroll
            for (int nt = 0; nt < 8; nt++)
                mma16816(sc[nt][0], sc[nt][1], sc[nt][2], sc[nt][3],
                         qa_h[s][0], qa_h[s][1], qa_h[s][2], qa_h[s][3], bf[nt][0], bf[nt][1]);
            #pragma unroll
            for (int nt = 0; nt < 8; nt++)
                mma16816(sc[nt][0], sc[nt][1], sc[nt][2], sc[nt][3],
                         qa_l[s][0], qa_l[s][1], qa_l[s][2], qa_l[s][3], bf[nt][0], bf[nt][1]);
            #pragma unroll
            for (int np = 0; np < 4; np++) {
                uint32_t r0, r1_, r2_, r3_;
                ldm_x4(r0, r1_, r2_, r3_, sKl[buf] + bBase + np*16*ATSB + s*32);
                bf[np*2+0][0] = r0;  bf[np*2+0][1] = r2_;
                bf[np*2+1][0] = r1_; bf[np*2+1][1] = r3_;
            }
            #pragma unroll
            for (int nt = 0; nt < 8; nt++)
                mma16816(sc[nt][0], sc[nt][1], sc[nt][2], sc[nt][3],
                         qa_h[s][0], qa_h[s][1], qa_h[s][2], qa_h[s][3], bf[nt][0], bf[nt][1]);
        }

        // ---- bias + mask (log2 domain) ----
        const int qx1 = S.qx[r1],   qy1 = S.qy[r1];
        const int qx2 = S.qx[r1+8], qy2 = S.qy[r1+8];
        #pragma unroll
        for (int nt = 0; nt < 8; nt++) {
            #pragma unroll
            for (int e = 0; e < 2; e++) {
                int c = nt*8 + (lane & 3)*2 + e;
                int kxv = S.kx[buf][c], kyv = S.ky[buf][c];
                bool valid = (kbase + c) < LKt;
                int rx1 = qx1 - kxv; rx1 = rx1 < -MD ? -MD : (rx1 > MD ? MD : rx1);
                int ry1 = qy1 - kyv; ry1 = ry1 < -MD ? -MD : (ry1 > MD ? MD : ry1);
                float b1v = S.bx[rx1 + MD] + S.by[ry1 + MD];
                sc[nt][e] = valid ? fmaf(sc[nt][e], CSC, b1v) : -1e30f;
                int rx2 = qx2 - kxv; rx2 = rx2 < -MD ? -MD : (rx2 > MD ? MD : rx2);
                int ry2 = qy2 - kyv; ry2 = ry2 < -MD ? -MD : (ry2 > MD ? MD : ry2);
                float b2v = S.bx[rx2 + MD] + S.by[ry2 + MD];
                sc[nt][2+e] = valid ? fmaf(sc[nt][2+e], CSC, b2v) : -1e30f;
            }
        }

        // ---- online softmax (log2 domain) ----
        float mx1 = -1e30f, mx2 = -1e30f;
        #pragma unroll
        for (int nt = 0; nt < 8; nt++) {
            mx1 = fmaxf(mx1, fmaxf(sc[nt][0], sc[nt][1]));
            mx2 = fmaxf(mx2, fmaxf(sc[nt][2], sc[nt][3]));
        }
        mx1 = fmaxf(mx1, __shfl_xor_sync(0xffffffffu, mx1, 1));
        mx1 = fmaxf(mx1, __shfl_xor_sync(0xffffffffu, mx1, 2));
        mx2 = fmaxf(mx2, __shfl_xor_sync(0xffffffffu, mx2, 1));
        mx2 = fmaxf(mx2, __shfl_xor_sync(0xffffffffu, mx2, 2));
        float mn1 = fmaxf(m1, mx1), mn2 = fmaxf(m2, mx2);
        float fac1 = exp2f(m1 - mn1), fac2 = exp2f(m2 - mn2);
        m1 = mn1; m2 = mn2;

        float rs1 = 0.f, rs2 = 0.f;
        #pragma unroll
        for (int nt = 0; nt < 8; nt++) {
            float p0 = exp2_poly(sc[nt][0] - m1);
            float p1 = exp2_poly(sc[nt][1] - m1);
            float p2 = exp2_poly(sc[nt][2] - m2);
            float p3 = exp2_poly(sc[nt][3] - m2);
            sc[nt][0] = p0; sc[nt][1] = p1; sc[nt][2] = p2; sc[nt][3] = p3;
            rs1 += p0 + p1; rs2 += p2 + p3;
        }
        rs1 += __shfl_xor_sync(0xffffffffu, rs1, 1);
        rs1 += __shfl_xor_sync(0xffffffffu, rs1, 2);
        rs2 += __shfl_xor_sync(0xffffffffu, rs2, 1);
        rs2 += __shfl_xor_sync(0xffffffffu, rs2, 2);
        l1 = l1 * fac1 + rs1;
        l2 = l2 * fac2 + rs2;
        #pragma unroll
        for (int d = 0; d < 8; d++) {
            oacc[d][0] *= fac1; oacc[d][1] *= fac1;
            oacc[d][2] *= fac2; oacc[d][3] *= fac2;
        }

        // ---- pack P to A-frags ----
        uint32_t pa[4][4];
        #pragma unroll
        for (int t = 0; t < 4; t++) {
            pa[t][0] = pack_bf16x2(sc[2*t][0],   sc[2*t][1]);
            pa[t][1] = pack_bf16x2(sc[2*t][2],   sc[2*t][3]);
            pa[t][2] = pack_bf16x2(sc[2*t+1][0], sc[2*t+1][1]);
            pa[t][3] = pack_bf16x2(sc[2*t+1][2], sc[2*t+1][3]);
        }

        // ---- O += P V (Vh then Vl) ----
        uint32_t vBase = (((lane >> 3) & 1)*8 + (lane & 7))*ATSB + (lane >> 4)*16;
        #pragma unroll
        for (int t = 0; t < 4; t++) {
            #pragma unroll
            for (int dp = 0; dp < 4; dp++) {
                uint32_t v0, v1, v2, v3;
                ldm_x4t(v0, v1, v2, v3, sVh[buf] + vBase + t*16*ATSB + dp*32);
                mma16816(oacc[dp*2][0], oacc[dp*2][1], oacc[dp*2][2], oacc[dp*2][3],
                         pa[t][0], pa[t][1], pa[t][2], pa[t][3], v0, v1);
                mma16816(oacc[dp*2+1][0], oacc[dp*2+1][1], oacc[dp*2+1][2], oacc[dp*2+1][3],
                         pa[t][0], pa[t][1], pa[t][2], pa[t][3], v2, v3);
            }
            #pragma unroll
            for (int dp = 0; dp < 4; dp++) {
                uint32_t v0, v1, v2, v3;
                ldm_x4t(v0, v1, v2, v3, sVl[buf] + vBase + t*16*ATSB + dp*32);
                mma16816(oacc[dp*2][0], oacc[dp*2][1], oacc[dp*2][2], oacc[dp*2][3],
                         pa[t][0], pa[t][1], pa[t][2], pa[t][3], v0, v1);
                mma16816(oacc[dp*2+1][0], oacc[dp*2+1][1], oacc[dp*2+1][2], oacc[dp*2+1][3],
                         pa[t][0], pa[t][1], pa[t][2], pa[t][3], v2, v3);
            }
        }
    }

    // ---- epilogue: normalize, split hi/lo, store ----
    float inv1 = 1.f / l1, inv2 = 1.f / l2;
    const int qrow1 = qbase + r1, qrow2 = qrow1 + 8;
    #pragma unroll
    for (int d = 0; d < 8; d++) {
        int col = hd + d*8 + (lane & 3)*2;
        {
            float v0 = oacc[d][0] * inv1, v1 = oacc[d][1] * inv1;
            __nv_bfloat16 h0,l0,h1,l1b;
            split_hilo(v0,h0,l0); split_hilo(v1,h1,l1b);
            size_t o = (size_t)(b*LQ + qrow1)*DM + col;
            __nv_bfloat162 ph; ph.x = h0; ph.y = h1;
            __nv_bfloat162 pl; pl.x = l0; pl.y = l1b;
            *reinterpret_cast<__nv_bfloat162*>(&ctxH[o]) = ph;
            *reinterpret_cast<__nv_bfloat162*>(&ctxL[o]) = pl;
        }
        {
            float v0 = oacc[d][2] * inv2, v1 = oacc[d][3] * inv2;
            __nv_bfloat16 h0,l0,h1,l1b;
            split_hilo(v0,h0,l0); split_hilo(v1,h1,l1b);
            size_t o = (size_t)(b*LQ + qrow2)*DM + col;
            __nv_bfloat162 ph; ph.x = h0; ph.y = h1;
            __nv_bfloat162 pl; pl.x = l0; pl.y = l1b;
            *reinterpret_cast<__nv_bfloat162*>(&ctxH[o]) = ph;
            *reinterpret_cast<__nv_bfloat162*>(&ctxL[o]) = pl;
        }
    }
}

// ================= fused add + LayerNorm =================
template<bool HILO>
__global__ void __launch_bounds__(256) addln_kernel(
    const float* __restrict__ A, const float* __restrict__ Cv,
    const float* __restrict__ g, const float* __restrict__ be,
    float* __restrict__ out, __nv_bfloat16* __restrict__ OH, __nv_bfloat16* __restrict__ OL)
{
    __shared__ float sred[256];
    const int row = blockIdx.x;
    const int tid = threadIdx.x;
    const size_t base = (size_t)row * DM;

    float x[3];
    #pragma unroll
    for (int i=0;i<3;i++) {
        int col = tid + 256*i;
        x[i] = A[base + col] + Cv[base + col];
    }
    float s = x[0] + x[1] + x[2];
    sred[tid] = s; __syncthreads();
    for (int off=128; off>0; off>>=1) {
        if (tid < off) sred[tid] += sred[tid+off];
        __syncthreads();
    }
    float mu = sred[0] * (1.f/DM);
    __syncthreads();
    float d0=x[0]-mu, d1=x[1]-mu, d2=x[2]-mu;
    sred[tid] = d0*d0 + d1*d1 + d2*d2; __syncthreads();
    for (int off=128; off>0; off>>=1) {
        if (tid < off) sred[tid] += sred[tid+off];
        __syncthreads();
    }
    float rs = rsqrtf(sred[0] * (1.f/DM) + 1e-5f);
    #pragma unroll
    for (int i=0;i<3;i++) {
        int col = tid + 256*i;
        float v = (x[i] - mu) * rs * g[col] + be[col];
        out[base + col] = v;
        if (HILO) {
            __nv_bfloat16 h, l; split_hilo(v, h, l);
            OH[base + col] = h; OL[base + col] = l;
        }
    }
}

// ================= launch =================
extern "C" void kernel_launch(void* const* d_in, const int* in_sizes, int n_in,
                              void* d_out, int out_size) {
    const float* docqa  = (const float*)d_in[0];
    const float* im     = (const float*)d_in[1];
    const int*   dqx    = (const int*)  d_in[2];
    const int*   dqy    = (const int*)  d_in[3];
    const int*   imx    = (const int*)  d_in[4];
    const int*   imy    = (const int*)  d_in[5];
    const float* Wq     = (const float*)d_in[6];
    const float* bq     = (const float*)d_in[7];
    const float* Wk     = (const float*)d_in[8];
    const float* bk     = (const float*)d_in[9];
    const float* Wv     = (const float*)d_in[10];
    const float* bv     = (const float*)d_in[11];
    const float* Wo     = (const float*)d_in[12];
    const float* bo     = (const float*)d_in[13];
    const float* bias_x = (const float*)d_in[14];
    const float* bias_y = (const float*)d_in[15];
    const float* W1     = (const float*)d_in[16];
    const float* b1     = (const float*)d_in[17];
    const float* W2     = (const float*)d_in[18];
    const float* b2     = (const float*)d_in[19];
    const float* g1     = (const float*)d_in[20];
    const float* be1    = (const float*)d_in[21];
    const float* g2     = (const float*)d_in[22];
    const float* be2    = (const float*)d_in[23];
    float* out = (float*)d_out;

    float *p_tmp, *p_src1;
    cudaGetSymbolAddress((void**)&p_tmp,  g_tmp);
    cudaGetSymbolAddress((void**)&p_src1, g_src1);

    __nv_bfloat16 *full_h,*full_l,*dq_h,*dq_l,*ctx_h,*ctx_l,*s1_h,*s1_l,*f1_h,*f1_l;
    __nv_bfloat16 *qh,*ql,*kh,*kl,*vh,*vl;
    __nv_bfloat16 *wqt_h,*wqt_l,*wkt_h,*wkt_l,*wvt_h,*wvt_l,*wot_h,*wot_l,*w1t_h,*w1t_l,*w2t_h,*w2t_l;
    cudaGetSymbolAddress((void**)&full_h, g_full_h); cudaGetSymbolAddress((void**)&full_l, g_full_l);
    cudaGetSymbolAddress((void**)&dq_h,   g_dq_h);   cudaGetSymbolAddress((void**)&dq_l,   g_dq_l);
    cudaGetSymbolAddress((void**)&qh, g_qh); cudaGetSymbolAddress((void**)&ql, g_ql);
    cudaGetSymbolAddress((void**)&kh, g_kh); cudaGetSymbolAddress((void**)&kl, g_kl);
    cudaGetSymbolAddress((void**)&vh, g_vh); cudaGetSymbolAddress((void**)&vl, g_vl);
    cudaGetSymbolAddress((void**)&ctx_h,  g_ctx_h);  cudaGetSymbolAddress((void**)&ctx_l,  g_ctx_l);
    cudaGetSymbolAddress((void**)&s1_h,   g_s1_h);   cudaGetSymbolAddress((void**)&s1_l,   g_s1_l);
    cudaGetSymbolAddress((void**)&f1_h,   g_f1_h);   cudaGetSymbolAddress((void**)&f1_l,   g_f1_l);
    cudaGetSymbolAddress((void**)&wqt_h,  g_wqt_h);  cudaGetSymbolAddress((void**)&wqt_l,  g_wqt_l);
    cudaGetSymbolAddress((void**)&wkt_h,  g_wkt_h);  cudaGetSymbolAddress((void**)&wkt_l,  g_wkt_l);
    cudaGetSymbolAddress((void**)&wvt_h,  g_wvt_h);  cudaGetSymbolAddress((void**)&wvt_l,  g_wvt_l);
    cudaGetSymbolAddress((void**)&wot_h,  g_wot_h);  cudaGetSymbolAddress((void**)&wot_l,  g_wot_l);
    cudaGetSymbolAddress((void**)&w1t_h,  g_w1t_h);  cudaGetSymbolAddress((void**)&w1t_l,  g_w1t_l);
    cudaGetSymbolAddress((void**)&w2t_h,  g_w2t_h);  cudaGetSymbolAddress((void**)&w2t_l,  g_w2t_l);

    cudaFuncSetAttribute(gemm_tc_kernel<false,false>, cudaFuncAttributeMaxDynamicSharedMemorySize, GEMM_SMEM);
    cudaFuncSetAttribute(gemm_tc_kernel<false,true >, cudaFuncAttributeMaxDynamicSharedMemorySize, GEMM_SMEM);
    cudaFuncSetAttribute(gemm_tc_kernel<true, true >, cudaFuncAttributeMaxDynamicSharedMemorySize, GEMM_SMEM);
    cudaFuncSetAttribute(attn_kernel, cudaFuncAttributeMaxDynamicSharedMemorySize, (int)sizeof(AttnSmem2));

    const int MQ = Bb*LQ;     // 2560
    const int MK = Bb*LKt;    // 7744

    // --- converts ---
    {
        int t4 = Bb*LKt*(DM/4);
        concat_conv_kernel<<<(t4+255)/256, 256>>>(im, docqa, full_h, full_l);
        int q4 = Bb*LQ*(DM/4);
        conv_hilo_kernel<<<(q4+255)/256, 256>>>(docqa, dq_h, dq_l, q4);
        dim3 tb(32,8);
        wtrans_conv_kernel<<<dim3(DM/32,   DM/32),   tb>>>(Wq, wqt_h, wqt_l, DM,   DM);
        wtrans_conv_kernel<<<dim3(DM/32,   DM/32),   tb>>>(Wk, wkt_h, wkt_l, DM,   DM);
        wtrans_conv_kernel<<<dim3(DM/32,   DM/32),   tb>>>(Wv, wvt_h, wvt_l, DM,   DM);
        wtrans_conv_kernel<<<dim3(DM/32,   DM/32),   tb>>>(Wo, wot_h, wot_l, DM,   DM);
        wtrans_conv_kernel<<<dim3(DFFn/32, DM/32),   tb>>>(W1, w1t_h, w1t_l, DM,   DFFn);
        wtrans_conv_kernel<<<dim3(DM/32,   DFFn/32), tb>>>(W2, w2t_h, w2t_l, DFFn, DM);
    }

    // --- projections (HMMA), emitting bf16 hi/lo ---
    gemm_tc_kernel<false,true><<<dim3(DM/128, (MQ+127)/128), 256, GEMM_SMEM>>>(
        dq_h, dq_l, wqt_h, wqt_l, bq, nullptr, qh, ql, MQ, DM, DM);
    gemm_tc_kernel<false,true><<<dim3(DM/128, (MK+127)/128), 256, GEMM_SMEM>>>(
        full_h, full_l, wkt_h, wkt_l, bk, nullptr, kh, kl, MK, DM, DM);
    gemm_tc_kernel<false,true><<<dim3(DM/128, (MK+127)/128), 256, GEMM_SMEM>>>(
        full_h, full_l, wvt_h, wvt_l, bv, nullptr, vh, vl, MK, DM, DM);

    // --- attention (HMMA) ---
    attn_kernel<<<dim3(LQ/64, Bb*NH), 128, sizeof(AttnSmem2)>>>(
        qh, ql, kh, kl, vh, vl, dqx, dqy, imx, imy, bias_x, bias_y, ctx_h, ctx_l);

    // --- output proj + LN + FFN + LN ---
    gemm_tc_kernel<false,false><<<dim3(DM/128, (MQ+127)/128), 256, GEMM_SMEM>>>(
        ctx_h, ctx_l, wot_h, wot_l, bo, p_tmp, nullptr, nullptr, MQ, DM, DM);
    addln_kernel<true><<<MQ, 256>>>(docqa, p_tmp, g1, be1, p_src1, s1_h, s1_l);
    gemm_tc_kernel<true,true><<<dim3(DFFn/128, (MQ+127)/128), 256, GEMM_SMEM>>>(
        s1_h, s1_l, w1t_h, w1t_l, b1, nullptr, f1_h, f1_l, MQ, DFFn, DM);
    gemm_tc_kernel<false,false><<<dim3(DM/128, (MQ+127)/128), 256, GEMM_SMEM>>>(
        f1_h, f1_l, w2t_h, w2t_l, b2, p_tmp, nullptr, nullptr, MQ, DM, DFFn);
    addln_kernel<false><<<MQ, 256>>>(p_src1, p_tmp, g2, be2, out, nullptr, nullptr);
}

// round 6
// speedup vs baseline: 6.0168x; 2.6283x over previous
#include <cuda_runtime.h>
#include <cuda_fp16.h>
#include <math.h>
#include <stdint.h>

#define Bb 4
#define LQ 640
#define LIMt 1296
#define LKt 1936
#define DM 768
#define NH 12
#define DKh 64
#define DFFn 3072
#define MD 100
#define KVS 1536   // kv row stride

// ================= helpers =================
__device__ __forceinline__ uint32_t smem_to_u32(const void* p) {
    uint32_t a;
    asm("{ .reg .u64 t; cvta.to.shared.u64 t, %1; cvt.u32.u64 %0, t; }" : "=r"(a) : "l"(p));
    return a;
}
__device__ __forceinline__ void cp_async16(uint32_t dst, const void* src, int src_bytes) {
    asm volatile("cp.async.cg.shared.global [%0], [%1], 16, %2;"
                 :: "r"(dst), "l"(src), "r"(src_bytes) : "memory");
}
__device__ __forceinline__ void cp_async4(uint32_t dst, const void* src, int src_bytes) {
    asm volatile("cp.async.ca.shared.global [%0], [%1], 4, %2;"
                 :: "r"(dst), "l"(src), "r"(src_bytes) : "memory");
}
__device__ __forceinline__ void cp_commit() {
    asm volatile("cp.async.commit_group;" ::: "memory");
}
template<int N>
__device__ __forceinline__ void cp_wait() {
    asm volatile("cp.async.wait_group %0;" :: "n"(N) : "memory");
}
__device__ __forceinline__ void ldm_x4(uint32_t& r0, uint32_t& r1, uint32_t& r2, uint32_t& r3,
                                       uint32_t addr) {
    asm volatile("ldmatrix.sync.aligned.m8n8.x4.shared.b16 {%0,%1,%2,%3}, [%4];"
                 : "=r"(r0), "=r"(r1), "=r"(r2), "=r"(r3) : "r"(addr));
}
__device__ __forceinline__ void ldm_x4t(uint32_t& r0, uint32_t& r1, uint32_t& r2, uint32_t& r3,
                                        uint32_t addr) {
    asm volatile("ldmatrix.sync.aligned.m8n8.x4.trans.shared.b16 {%0,%1,%2,%3}, [%4];"
                 : "=r"(r0), "=r"(r1), "=r"(r2), "=r"(r3) : "r"(addr));
}
__device__ __forceinline__ void mma16816(float& d0, float& d1, float& d2, float& d3,
                                         uint32_t a0, uint32_t a1, uint32_t a2, uint32_t a3,
                                         uint32_t b0, uint32_t b1) {
    asm volatile("mma.sync.aligned.m16n8k16.row.col.f32.f16.f16.f32 "
                 "{%0,%1,%2,%3}, {%4,%5,%6,%7}, {%8,%9}, {%0,%1,%2,%3};"
                 : "+f"(d0), "+f"(d1), "+f"(d2), "+f"(d3)
                 : "r"(a0), "r"(a1), "r"(a2), "r"(a3), "r"(b0), "r"(b1));
}
__device__ __forceinline__ float exp2_poly(float a) {
    a = fmaxf(a, -126.f);
    float z = a + 12582912.f;
    int ir = __float_as_int(z) - 0x4B400000;
    float r = z - 12582912.f;
    float f = a - r;
    float p = 0.0096181291f;
    p = fmaf(p, f, 0.0555041087f);
    p = fmaf(p, f, 0.2402265070f);
    p = fmaf(p, f, 0.6931471806f);
    p = fmaf(p, f, 1.0f);
    return p * __int_as_float((ir + 127) << 23);
}

// ================= scratch =================
__device__ float g_tmp [Bb*LQ*DM];
__device__ float g_src1[Bb*LQ*DM];
__device__ float g_bkv [KVS];

__device__ __half g_full[Bb*LKt*DM];
__device__ __half g_dq  [Bb*LQ*DM];
__device__ __half g_q   [Bb*LQ*DM];
__device__ __half g_kv  [Bb*LKt*KVS];
__device__ __half g_ctx [Bb*LQ*DM];
__device__ __half g_s1  [Bb*LQ*DM];
__device__ __half g_f1  [Bb*LQ*DFFn];
__device__ __half g_wqt [DM*DM];
__device__ __half g_wkvt[KVS*DM];
__device__ __half g_wot [DM*DM];
__device__ __half g_w1t [DFFn*DM];
__device__ __half g_w2t [DM*DFFn];

// ================= converts =================
__global__ void conv_f16_kernel(const float* __restrict__ X, __half* __restrict__ O, int n4) {
    int i = blockIdx.x * blockDim.x + threadIdx.x;
    if (i >= n4) return;
    float4 v = ((const float4*)X)[i];
    __half2* o = (__half2*)(O + (size_t)i*4);
    o[0] = __floats2half2_rn(v.x, v.y);
    o[1] = __floats2half2_rn(v.z, v.w);
}

__global__ void concat_f16_kernel(const float* __restrict__ im, const float* __restrict__ doc,
                                  __half* __restrict__ O) {
    int i = blockIdx.x * blockDim.x + threadIdx.x;
    const int total4 = Bb*LKt*(DM/4);
    if (i >= total4) return;
    int d4 = i % (DM/4); int bt = i / (DM/4);
    int b = bt / LKt, t = bt % LKt;
    const float* src = (t < LIMt) ? im + ((size_t)b*LIMt + t)*DM
                                  : doc + ((size_t)b*LQ + (t - LIMt))*DM;
    float4 v = *(const float4*)(src + d4*4);
    __half2* o = (__half2*)(O + (size_t)i*4);
    o[0] = __floats2half2_rn(v.x, v.y);
    o[1] = __floats2half2_rn(v.z, v.w);
}

__global__ void wtrans_f16_kernel(const float* __restrict__ W, __half* __restrict__ T,
                                  int K, int N) {
    __shared__ float t[32][33];
    int n0 = blockIdx.x * 32, k0 = blockIdx.y * 32;
    int tx = threadIdx.x, ty = threadIdx.y;  // 32 x 8
    #pragma unroll
    for (int i = 0; i < 4; i++) {
        int k = ty + i*8;
        t[k][tx] = W[(size_t)(k0 + k)*N + n0 + tx];
    }
    __syncthreads();
    #pragma unroll
    for (int i = 0; i < 4; i++) {
        int n = ty + i*8;
        T[(size_t)(n0 + n)*K + k0 + tx] = __float2half_rn(t[tx][n]);
    }
}

__global__ void bias_cat_kernel(const float* __restrict__ bk, const float* __restrict__ bv,
                                float* __restrict__ bkv) {
    int i = blockIdx.x * blockDim.x + threadIdx.x;
    if (i < DM) bkv[i] = bk[i];
    else if (i < KVS) bkv[i] = bv[i - DM];
}

// ================= single-pass fp16 HMMA GEMM =================
#define KT 64
#define ROWB 144
#define TILEB (128*ROWB)
#define GEMM_SMEM (4*TILEB)

template<int OUTM, bool RELU>   // OUTM: 0 -> f32 C, 1 -> f16 O16
__global__ void __launch_bounds__(256) gemm_f16_kernel(
    const __half* __restrict__ A, const __half* __restrict__ Bw,
    const float* __restrict__ bias,
    float* __restrict__ C, __half* __restrict__ O16,
    int M, int N, int K)
{
    extern __shared__ char smem[];
    const uint32_t sbase = smem_to_u32(smem);
    const int tid = threadIdx.x, wid = tid >> 5, lane = tid & 31;
    const int wm = wid & 1, wn = wid >> 1;
    const int m0 = blockIdx.y * 128, n0 = blockIdx.x * 128;
    const int KC = K / KT;

    float acc[4][4][4];
    #pragma unroll
    for (int i=0;i<4;i++)
        #pragma unroll
        for (int j=0;j<4;j++)
            #pragma unroll
            for (int r=0;r<4;r++) acc[i][j][r] = 0.f;

    const int lr = tid >> 3;
    const int lc = tid & 7;

    auto issue_chunk = [&](int c) {
        const int buf = c & 1;
        const int k0 = c * KT;
        uint32_t sA = sbase + buf * 2 * TILEB;
        uint32_t sB = sA + TILEB;
        #pragma unroll
        for (int it = 0; it < 4; it++) {
            int r = lr + it * 32;
            int gm = m0 + r;
            cp_async16(sA + r*ROWB + lc*16,
                       A + (size_t)gm * K + k0 + lc*8,
                       gm < M ? 16 : 0);
        }
        #pragma unroll
        for (int it = 0; it < 4; it++) {
            int r = lr + it * 32;
            cp_async16(sB + r*ROWB + lc*16,
                       Bw + (size_t)(n0 + r) * K + k0 + lc*8, 16);
        }
        cp_commit();
    };

    issue_chunk(0);
    for (int c = 0; c < KC; c++) {
        if (c + 1 < KC) { issue_chunk(c + 1); cp_wait<1>(); }
        else            { cp_wait<0>(); }
        __syncthreads();

        const int buf = c & 1;
        uint32_t sA = sbase + buf * 2 * TILEB;
        uint32_t sB = sA + TILEB;
        uint32_t aRowBase = sA + (wm*64 + (lane & 15)) * ROWB + (lane >> 4) * 16;
        uint32_t bRowBase = sB + (wn*32 + (lane & 15)) * ROWB + (lane >> 4) * 16;

        #pragma unroll
        for (int ks = 0; ks < 4; ks++) {
            const int kb = ks * 32;
            uint32_t bfr[4][2];
            #pragma unroll
            for (int np = 0; np < 2; np++) {
                uint32_t r0, r1, r2, r3;
                ldm_x4(r0, r1, r2, r3, bRowBase + np*16*ROWB + kb);
                bfr[np*2+0][0] = r0; bfr[np*2+0][1] = r2;
                bfr[np*2+1][0] = r1; bfr[np*2+1][1] = r3;
            }
            #pragma unroll
            for (int mt = 0; mt < 4; mt++) {
                uint32_t a0, a1, a2, a3;
                ldm_x4(a0, a1, a2, a3, aRowBase + mt*16*ROWB + kb);
                #pragma unroll
                for (int nt = 0; nt < 4; nt++)
                    mma16816(acc[mt][nt][0], acc[mt][nt][1], acc[mt][nt][2], acc[mt][nt][3],
                             a0, a1, a2, a3, bfr[nt][0], bfr[nt][1]);
            }
        }
        __syncthreads();
    }

    const int mr = lane >> 2, nc = (lane & 3) * 2;
    #pragma unroll
    for (int mt = 0; mt < 4; mt++) {
        #pragma unroll
        for (int half = 0; half < 2; half++) {
            int m = m0 + wm*64 + mt*16 + mr + half*8;
            if (m >= M) continue;
            #pragma unroll
            for (int nt = 0; nt < 4; nt++) {
                int n = n0 + wn*32 + nt*8 + nc;
                float v0 = acc[mt][nt][half*2+0] + bias[n];
                float v1 = acc[mt][nt][half*2+1] + bias[n+1];
                if (RELU) { v0 = fmaxf(v0, 0.f); v1 = fmaxf(v1, 0.f); }
                size_t o = (size_t)m * N + n;
                if (OUTM == 1) {
                    *reinterpret_cast<__half2*>(O16 + o) = __floats2half2_rn(v0, v1);
                } else {
                    C[o] = v0; C[o+1] = v1;
                }
            }
        }
    }
}

// ================= fp16 HMMA flash attention =================
#define ATS 72
#define ATSB 144

struct AttnSmem3 {
    __half Q[64*ATS];
    __half K[2][64*ATS], V[2][64*ATS];
    float bx[201], by[201];
    int qx[64], qy[64];
    int kx[2][64], ky[2][64];
};

#define CSC 0.18033688011116f   /* 0.125 * log2(e) */

__global__ void __launch_bounds__(128) attn_kernel(
    const __half* __restrict__ qg, const __half* __restrict__ kvg,
    const int* __restrict__ dqx, const int* __restrict__ dqy,
    const int* __restrict__ imx, const int* __restrict__ imy,
    const float* __restrict__ bias_x, const float* __restrict__ bias_y,
    __half* __restrict__ ctx)
{
    extern __shared__ char smem_raw[];
    AttnSmem3& S = *reinterpret_cast<AttnSmem3*>(smem_raw);
    const int tid = threadIdx.x;
    const int lane = tid & 31, w = tid >> 5;
    const int qt = blockIdx.x;
    const int bh = blockIdx.y;
    const int b = bh / NH, h = bh % NH;
    const int qbase = qt * 64;
    const int bLK = b * LKt;
    const int hd = h * DKh;

    const uint32_t sQ = smem_to_u32(S.Q);
    uint32_t sK[2] = { smem_to_u32(S.K[0]), smem_to_u32(S.K[1]) };
    uint32_t sV[2] = { smem_to_u32(S.V[0]), smem_to_u32(S.V[1]) };
    uint32_t sKx[2] = { smem_to_u32(S.kx[0]), smem_to_u32(S.kx[1]) };
    uint32_t sKy[2] = { smem_to_u32(S.ky[0]), smem_to_u32(S.ky[1]) };

    #pragma unroll
    for (int it = 0; it < 4; it++) {
        int ch = tid + it*128;
        int row = ch >> 3, off = (ch & 7) * 8;
        size_t g = (size_t)(b*LQ + qbase + row)*DM + hd + off;
        *(float4*)((char*)S.Q + row*ATSB + off*2) = *(const float4*)(qg + g);
    }
    const float LOG2E = 1.4426950408889634f;
    for (int i = tid; i < 201; i += 128) {
        S.bx[i] = bias_x[i*NH + h] * LOG2E;
        S.by[i] = bias_y[i*NH + h] * LOG2E;
    }
    if (tid < 64) S.qx[tid] = dqx[b*LQ + qbase + tid];
    else if (tid < 128) S.qy[tid-64] = dqy[b*LQ + qbase + (tid-64)];

    auto issue_kv = [&](int kt) {
        const int buf = kt & 1;
        const int kbase = kt * 64;
        #pragma unroll
        for (int it = 0; it < 4; it++) {
            int ch = tid + it*128;
            int row = ch >> 3, off = (ch & 7) * 8;
            int kg = kbase + row;
            int nb = kg < LKt ? 16 : 0;
            size_t g = (size_t)(bLK + kg)*KVS + hd + off;
            uint32_t so = row*ATSB + off*2;
            cp_async16(sK[buf] + so, kvg + g, nb);
            cp_async16(sV[buf] + so, kvg + g + DM, nb);
        }
        {
            int j = tid & 63;
            int kg = kbase + j;
            const int* src;
            if (tid < 64) src = (kg < LIMt) ? (imx + b*LIMt + kg) : (dqx + b*LQ + (kg - LIMt));
            else          src = (kg < LIMt) ? (imy + b*LIMt + kg) : (dqy + b*LQ + (kg - LIMt));
            uint32_t dst = (tid < 64 ? sKx[buf] : sKy[buf]) + j*4;
            cp_async4(dst, src, kg < LKt ? 4 : 0);
        }
        cp_commit();
    };

    issue_kv(0);
    __syncthreads();

    uint32_t qa[4][4];
    {
        uint32_t aBase = (w*16 + (lane & 15))*ATSB + (lane >> 4)*16;
        #pragma unroll
        for (int s = 0; s < 4; s++)
            ldm_x4(qa[s][0], qa[s][1], qa[s][2], qa[s][3], sQ + aBase + s*32);
    }

    const int r1 = w*16 + (lane >> 2);
    float oacc[8][4];
    #pragma unroll
    for (int d=0; d<8; d++)
        #pragma unroll
        for (int r=0; r<4; r++) oacc[d][r] = 0.f;
    float m1 = -1e30f, m2 = -1e30f, l1 = 0.f, l2 = 0.f;

    const int NT = (LKt + 63) / 64;
    for (int kt = 0; kt < NT; kt++) {
        if (kt > 0) __syncthreads();
        if (kt + 1 < NT) { issue_kv(kt + 1); cp_wait<1>(); }
        else             { cp_wait<0>(); }
        __syncthreads();

        const int buf = kt & 1;
        const int kbase = kt * 64;

        float sc[8][4];
        #pragma unroll
        for (int nt=0; nt<8; nt++)
            #pragma unroll
            for (int r=0; r<4; r++) sc[nt][r] = 0.f;

        uint32_t bBase = (lane & 15)*ATSB + (lane >> 4)*16;
        #pragma unroll
        for (int s = 0; s < 4; s++) {
            uint32_t bf[8][2];
            #pragma unroll
            for (int np = 0; np < 4; np++) {
                uint32_t r0, r1_, r2_, r3_;
                ldm_x4(r0, r1_, r2_, r3_, sK[buf] + bBase + np*16*ATSB + s*32);
                bf[np*2+0][0] = r0;  bf[np*2+0][1] = r2_;
                bf[np*2+1][0] = r1_; bf[np*2+1][1] = r3_;
            }
            #pragma unroll
            for (int nt = 0; nt < 8; nt++)
                mma16816(sc[nt][0], sc[nt][1], sc[nt][2], sc[nt][3],
                         qa[s][0], qa[s][1], qa[s][2], qa[s][3], bf[nt][0], bf[nt][1]);
        }

        const int qx1 = S.qx[r1],   qy1 = S.qy[r1];
        const int qx2 = S.qx[r1+8], qy2 = S.qy[r1+8];
        #pragma unroll
        for (int nt = 0; nt < 8; nt++) {
            #pragma unroll
            for (int e = 0; e < 2; e++) {
                int c = nt*8 + (lane & 3)*2 + e;
                int kxv = S.kx[buf][c], kyv = S.ky[buf][c];
                bool valid = (kbase + c) < LKt;
                int rx1 = qx1 - kxv; rx1 = rx1 < -MD ? -MD : (rx1 > MD ? MD : rx1);
                int ry1 = qy1 - kyv; ry1 = ry1 < -MD ? -MD : (ry1 > MD ? MD : ry1);
                float b1v = S.bx[rx1 + MD] + S.by[ry1 + MD];
                sc[nt][e] = valid ? fmaf(sc[nt][e], CSC, b1v) : -1e30f;
                int rx2 = qx2 - kxv; rx2 = rx2 < -MD ? -MD : (rx2 > MD ? MD : rx2);
                int ry2 = qy2 - kyv; ry2 = ry2 < -MD ? -MD : (ry2 > MD ? MD : ry2);
                float b2v = S.bx[rx2 + MD] + S.by[ry2 + MD];
                sc[nt][2+e] = valid ? fmaf(sc[nt][2+e], CSC, b2v) : -1e30f;
            }
        }

        float mx1 = -1e30f, mx2 = -1e30f;
        #pragma unroll
        for (int nt = 0; nt < 8; nt++) {
            mx1 = fmaxf(mx1, fmaxf(sc[nt][0], sc[nt][1]));
            mx2 = fmaxf(mx2, fmaxf(sc[nt][2], sc[nt][3]));
        }
        mx1 = fmaxf(mx1, __shfl_xor_sync(0xffffffffu, mx1, 1));
        mx1 = fmaxf(mx1, __shfl_xor_sync(0xffffffffu, mx1, 2));
        mx2 = fmaxf(mx2, __shfl_xor_sync(0xffffffffu, mx2, 1));
        mx2 = fmaxf(mx2, __shfl_xor_sync(0xffffffffu, mx2, 2));
        float mn1 = fmaxf(m1, mx1), mn2 = fmaxf(m2, mx2);
        float fac1 = exp2f(m1 - mn1), fac2 = exp2f(m2 - mn2);
        m1 = mn1; m2 = mn2;

        float rs1 = 0.f, rs2 = 0.f;
        #pragma unroll
        for (int nt = 0; nt < 8; nt++) {
            float p0 = exp2_poly(sc[nt][0] - m1);
            float p1 = exp2_poly(sc[nt][1] - m1);
            float p2 = exp2_poly(sc[nt][2] - m2);
            float p3 = exp2_poly(sc[nt][3] - m2);
            sc[nt][0] = p0; sc[nt][1] = p1; sc[nt][2] = p2; sc[nt][3] = p3;
            rs1 += p0 + p1; rs2 += p2 + p3;
        }
        rs1 += __shfl_xor_sync(0xffffffffu, rs1, 1);
        rs1 += __shfl_xor_sync(0xffffffffu, rs1, 2);
        rs2 += __shfl_xor_sync(0xffffffffu, rs2, 1);
        rs2 += __shfl_xor_sync(0xffffffffu, rs2, 2);
        l1 = l1 * fac1 + rs1;
        l2 = l2 * fac2 + rs2;
        #pragma unroll
        for (int d = 0; d < 8; d++) {
            oacc[d][0] *= fac1; oacc[d][1] *= fac1;
            oacc[d][2] *= fac2; oacc[d][3] *= fac2;
        }

        uint32_t pa[4][4];
        #pragma unroll
        for (int t = 0; t < 4; t++) {
            __half2 h0 = __floats2half2_rn(sc[2*t][0],   sc[2*t][1]);
            __half2 h1 = __floats2half2_rn(sc[2*t][2],   sc[2*t][3]);
            __half2 h2 = __floats2half2_rn(sc[2*t+1][0], sc[2*t+1][1]);
            __half2 h3 = __floats2half2_rn(sc[2*t+1][2], sc[2*t+1][3]);
            pa[t][0] = *reinterpret_cast<uint32_t*>(&h0);
            pa[t][1] = *reinterpret_cast<uint32_t*>(&h1);
            pa[t][2] = *reinterpret_cast<uint32_t*>(&h2);
            pa[t][3] = *reinterpret_cast<uint32_t*>(&h3);
        }

        uint32_t vBase = (((lane >> 3) & 1)*8 + (lane & 7))*ATSB + (lane >> 4)*16;
        #pragma unroll
        for (int t = 0; t < 4; t++) {
            #pragma unroll
            for (int dp = 0; dp < 4; dp++) {
                uint32_t v0, v1, v2, v3;
                ldm_x4t(v0, v1, v2, v3, sV[buf] + vBase + t*16*ATSB + dp*32);
                mma16816(oacc[dp*2][0], oacc[dp*2][1], oacc[dp*2][2], oacc[dp*2][3],
                         pa[t][0], pa[t][1], pa[t][2], pa[t][3], v0, v1);
                mma16816(oacc[dp*2+1][0], oacc[dp*2+1][1], oacc[dp*2+1][2], oacc[dp*2+1][3],
                         pa[t][0], pa[t][1], pa[t][2], pa[t][3], v2, v3);
            }
        }
    }

    float inv1 = 1.f / l1, inv2 = 1.f / l2;
    const int qrow1 = qbase + r1, qrow2 = qrow1 + 8;
    #pragma unroll
    for (int d = 0; d < 8; d++) {
        int col = hd + d*8 + (lane & 3)*2;
        {
            size_t o = (size_t)(b*LQ + qrow1)*DM + col;
            *reinterpret_cast<__half2*>(ctx + o) =
                __floats2half2_rn(oacc[d][0]*inv1, oacc[d][1]*inv1);
        }
        {
            size_t o = (size_t)(b*LQ + qrow2)*DM + col;
            *reinterpret_cast<__half2*>(ctx + o) =
                __floats2half2_rn(oacc[d][2]*inv2, oacc[d][3]*inv2);
        }
    }
}

// ================= fused add + LayerNorm =================
template<bool F16OUT>
__global__ void __launch_bounds__(256) addln_kernel(
    const float* __restrict__ A, const float* __restrict__ Cv,
    const float* __restrict__ g, const float* __restrict__ be,
    float* __restrict__ out, __half* __restrict__ O16)
{
    __shared__ float sred[256];
    const int row = blockIdx.x;
    const int tid = threadIdx.x;
    const size_t base = (size_t)row * DM;

    float x[3];
    #pragma unroll
    for (int i=0;i<3;i++) {
        int col = tid + 256*i;
        x[i] = A[base + col] + Cv[base + col];
    }
    float s = x[0] + x[1] + x[2];
    sred[tid] = s; __syncthreads();
    for (int off=128; off>0; off>>=1) {
        if (tid < off) sred[tid] += sred[tid+off];
        __syncthreads();
    }
    float mu = sred[0] * (1.f/DM);
    __syncthreads();
    float d0=x[0]-mu, d1=x[1]-mu, d2=x[2]-mu;
    sred[tid] = d0*d0 + d1*d1 + d2*d2; __syncthreads();
    for (int off=128; off>0; off>>=1) {
        if (tid < off) sred[tid] += sred[tid+off];
        __syncthreads();
    }
    float rs = rsqrtf(sred[0] * (1.f/DM) + 1e-5f);
    #pragma unroll
    for (int i=0;i<3;i++) {
        int col = tid + 256*i;
        float v = (x[i] - mu) * rs * g[col] + be[col];
        out[base + col] = v;
        if (F16OUT) O16[base + col] = __float2half_rn(v);
    }
}

// ================= launch =================
extern "C" void kernel_launch(void* const* d_in, const int* in_sizes, int n_in,
                              void* d_out, int out_size) {
    const float* docqa  = (const float*)d_in[0];
    const float* im     = (const float*)d_in[1];
    const int*   dqx    = (const int*)  d_in[2];
    const int*   dqy    = (const int*)  d_in[3];
    const int*   imx    = (const int*)  d_in[4];
    const int*   imy    = (const int*)  d_in[5];
    const float* Wq     = (const float*)d_in[6];
    const float* bq     = (const float*)d_in[7];
    const float* Wk     = (const float*)d_in[8];
    const float* bk     = (const float*)d_in[9];
    const float* Wv     = (const float*)d_in[10];
    const float* bv     = (const float*)d_in[11];
    const float* Wo     = (const float*)d_in[12];
    const float* bo     = (const float*)d_in[13];
    const float* bias_x = (const float*)d_in[14];
    const float* bias_y = (const float*)d_in[15];
    const float* W1     = (const float*)d_in[16];
    const float* b1     = (const float*)d_in[17];
    const float* W2     = (const float*)d_in[18];
    const float* b2     = (const float*)d_in[19];
    const float* g1     = (const float*)d_in[20];
    const float* be1    = (const float*)d_in[21];
    const float* g2     = (const float*)d_in[22];
    const float* be2    = (const float*)d_in[23];
    float* out = (float*)d_out;

    float *p_tmp, *p_src1, *p_bkv;
    cudaGetSymbolAddress((void**)&p_tmp,  g_tmp);
    cudaGetSymbolAddress((void**)&p_src1, g_src1);
    cudaGetSymbolAddress((void**)&p_bkv,  g_bkv);

    __half *full, *dq, *q, *kv, *ctx, *s1, *f1;
    __half *wqt, *wkvt, *wot, *w1t, *w2t;
    cudaGetSymbolAddress((void**)&full, g_full);
    cudaGetSymbolAddress((void**)&dq,   g_dq);
    cudaGetSymbolAddress((void**)&q,    g_q);
    cudaGetSymbolAddress((void**)&kv,   g_kv);
    cudaGetSymbolAddress((void**)&ctx,  g_ctx);
    cudaGetSymbolAddress((void**)&s1,   g_s1);
    cudaGetSymbolAddress((void**)&f1,   g_f1);
    cudaGetSymbolAddress((void**)&wqt,  g_wqt);
    cudaGetSymbolAddress((void**)&wkvt, g_wkvt);
    cudaGetSymbolAddress((void**)&wot,  g_wot);
    cudaGetSymbolAddress((void**)&w1t,  g_w1t);
    cudaGetSymbolAddress((void**)&w2t,  g_w2t);

    cudaFuncSetAttribute(gemm_f16_kernel<0,false>, cudaFuncAttributeMaxDynamicSharedMemorySize, GEMM_SMEM);
    cudaFuncSetAttribute(gemm_f16_kernel<1,false>, cudaFuncAttributeMaxDynamicSharedMemorySize, GEMM_SMEM);
    cudaFuncSetAttribute(gemm_f16_kernel<1,true >, cudaFuncAttributeMaxDynamicSharedMemorySize, GEMM_SMEM);
    cudaFuncSetAttribute(attn_kernel, cudaFuncAttributeMaxDynamicSharedMemorySize, (int)sizeof(AttnSmem3));

    const int MQ = Bb*LQ;     // 2560
    const int MK = Bb*LKt;    // 7744
    dim3 tb(32,8);

    // launches 0-4 (launch #5 = KV GEMM -> profiled by ncu -s 5 -c 1)
    concat_f16_kernel<<<(Bb*LKt*(DM/4)+255)/256, 256>>>(im, docqa, full);
    conv_f16_kernel<<<(Bb*LQ*(DM/4)+255)/256, 256>>>(docqa, dq, Bb*LQ*(DM/4));
    wtrans_f16_kernel<<<dim3(DM/32, DM/32), tb>>>(Wk, wkvt, DM, DM);
    wtrans_f16_kernel<<<dim3(DM/32, DM/32), tb>>>(Wv, wkvt + (size_t)DM*DM, DM, DM);
    bias_cat_kernel<<<(KVS+255)/256, 256>>>(bk, bv, p_bkv);

    gemm_f16_kernel<1,false><<<dim3(KVS/128, (MK+127)/128), 256, GEMM_SMEM>>>(
        full, wkvt, p_bkv, nullptr, kv, MK, KVS, DM);

    wtrans_f16_kernel<<<dim3(DM/32, DM/32), tb>>>(Wq, wqt, DM, DM);
    gemm_f16_kernel<1,false><<<dim3(DM/128, (MQ+127)/128), 256, GEMM_SMEM>>>(
        dq, wqt, bq, nullptr, q, MQ, DM, DM);

    wtrans_f16_kernel<<<dim3(DM/32,   DM/32),   tb>>>(Wo, wot, DM, DM);
    wtrans_f16_kernel<<<dim3(DFFn/32, DM/32),   tb>>>(W1, w1t, DM, DFFn);
    wtrans_f16_kernel<<<dim3(DM/32,   DFFn/32), tb>>>(W2, w2t, DFFn, DM);

    attn_kernel<<<dim3(LQ/64, Bb*NH), 128, sizeof(AttnSmem3)>>>(
        q, kv, dqx, dqy, imx, imy, bias_x, bias_y, ctx);

    gemm_f16_kernel<0,false><<<dim3(DM/128, (MQ+127)/128), 256, GEMM_SMEM>>>(
        ctx, wot, bo, p_tmp, nullptr, MQ, DM, DM);
    addln_kernel<true><<<MQ, 256>>>(docqa, p_tmp, g1, be1, p_src1, s1);
    gemm_f16_kernel<1,true><<<dim3(DFFn/128, (MQ+127)/128), 256, GEMM_SMEM>>>(
        s1, w1t, b1, nullptr, f1, MQ, DFFn, DM);
    gemm_f16_kernel<0,false><<<dim3(DM/128, (MQ+127)/128), 256, GEMM_SMEM>>>(
        f1, w2t, b2, p_tmp, nullptr, MQ, DM, DFFn);
    addln_kernel<false><<<MQ, 256>>>(p_src1, p_tmp, g2, be2, out, nullptr);
}

// round 7
// speedup vs baseline: 6.7482x; 1.1215x over previous
#include <cuda_runtime.h>
#include <cuda_fp16.h>
#include <math.h>
#include <stdint.h>

#define Bb 4
#define LQ 640
#define LIMt 1296
#define LKt 1936
#define DM 768
#define NH 12
#define DKh 64
#define DFFn 3072
#define MD 100
#define KVS 1536   // kv row stride

// ================= helpers =================
__device__ __forceinline__ uint32_t smem_to_u32(const void* p) {
    uint32_t a;
    asm("{ .reg .u64 t; cvta.to.shared.u64 t, %1; cvt.u32.u64 %0, t; }" : "=r"(a) : "l"(p));
    return a;
}
__device__ __forceinline__ void cp_async16(uint32_t dst, const void* src, int src_bytes) {
    asm volatile("cp.async.cg.shared.global [%0], [%1], 16, %2;"
                 :: "r"(dst), "l"(src), "r"(src_bytes) : "memory");
}
__device__ __forceinline__ void cp_async4(uint32_t dst, const void* src, int src_bytes) {
    asm volatile("cp.async.ca.shared.global [%0], [%1], 4, %2;"
                 :: "r"(dst), "l"(src), "r"(src_bytes) : "memory");
}
__device__ __forceinline__ void cp_commit() {
    asm volatile("cp.async.commit_group;" ::: "memory");
}
template<int N>
__device__ __forceinline__ void cp_wait() {
    asm volatile("cp.async.wait_group %0;" :: "n"(N) : "memory");
}
__device__ __forceinline__ void ldm_x4(uint32_t& r0, uint32_t& r1, uint32_t& r2, uint32_t& r3,
                                       uint32_t addr) {
    asm volatile("ldmatrix.sync.aligned.m8n8.x4.shared.b16 {%0,%1,%2,%3}, [%4];"
                 : "=r"(r0), "=r"(r1), "=r"(r2), "=r"(r3) : "r"(addr));
}
__device__ __forceinline__ void ldm_x4t(uint32_t& r0, uint32_t& r1, uint32_t& r2, uint32_t& r3,
                                        uint32_t addr) {
    asm volatile("ldmatrix.sync.aligned.m8n8.x4.trans.shared.b16 {%0,%1,%2,%3}, [%4];"
                 : "=r"(r0), "=r"(r1), "=r"(r2), "=r"(r3) : "r"(addr));
}
__device__ __forceinline__ void mma16816(float& d0, float& d1, float& d2, float& d3,
                                         uint32_t a0, uint32_t a1, uint32_t a2, uint32_t a3,
                                         uint32_t b0, uint32_t b1) {
    asm volatile("mma.sync.aligned.m16n8k16.row.col.f32.f16.f16.f32 "
                 "{%0,%1,%2,%3}, {%4,%5,%6,%7}, {%8,%9}, {%0,%1,%2,%3};"
                 : "+f"(d0), "+f"(d1), "+f"(d2), "+f"(d3)
                 : "r"(a0), "r"(a1), "r"(a2), "r"(a3), "r"(b0), "r"(b1));
}
__device__ __forceinline__ float exp2_poly(float a) {
    a = fmaxf(a, -126.f);
    float z = a + 12582912.f;
    int ir = __float_as_int(z) - 0x4B400000;
    float r = z - 12582912.f;
    float f = a - r;
    float p = 0.0096181291f;
    p = fmaf(p, f, 0.0555041087f);
    p = fmaf(p, f, 0.2402265070f);
    p = fmaf(p, f, 0.6931471806f);
    p = fmaf(p, f, 1.0f);
    return p * __int_as_float((ir + 127) << 23);
}

// ================= scratch =================
__device__ float g_tmp [Bb*LQ*DM];
__device__ float g_src1[Bb*LQ*DM];
__device__ float g_bkv [KVS];

__device__ __half g_full[Bb*LKt*DM];
__device__ __half g_q   [Bb*LQ*DM];
__device__ __half g_kv  [Bb*LKt*KVS];
__device__ __half g_ctx [Bb*LQ*DM];
__device__ __half g_s1  [Bb*LQ*DM];
__device__ __half g_f1  [Bb*LQ*DFFn];
// weights in ORIGINAL [K][N] layout, fp16
__device__ __half g_wq16[DM*DM];
__device__ __half g_wk16[DM*DM];
__device__ __half g_wv16[DM*DM];
__device__ __half g_wo16[DM*DM];
__device__ __half g_w116[DM*DFFn];
__device__ __half g_w216[DFFn*DM];

// ================= converts =================
__global__ void concat_f16_kernel(const float* __restrict__ im, const float* __restrict__ doc,
                                  __half* __restrict__ O) {
    int i = blockIdx.x * blockDim.x + threadIdx.x;
    const int total4 = Bb*LKt*(DM/4);
    if (i >= total4) return;
    int d4 = i % (DM/4); int bt = i / (DM/4);
    int b = bt / LKt, t = bt % LKt;
    const float* src = (t < LIMt) ? im + ((size_t)b*LIMt + t)*DM
                                  : doc + ((size_t)b*LQ + (t - LIMt))*DM;
    float4 v = *(const float4*)(src + d4*4);
    __half2* o = (__half2*)(O + (size_t)i*4);
    o[0] = __floats2half2_rn(v.x, v.y);
    o[1] = __floats2half2_rn(v.z, v.w);
}

// one kernel: all 6 weights fp32->fp16 (layout preserved) + bias concat
#define SWF4   147456                 // 768*768/4
#define W1F4   589824                 // 768*3072/4
#define SEG_W1 (4*SWF4)               // 589824
#define SEG_W2 (SEG_W1 + W1F4)       // 1179648
#define SEG_B  (SEG_W2 + W1F4)       // 1769472
#define SEG_END (SEG_B + KVS/4)      // 1769856

__global__ void wconv_all_kernel(
    const float* __restrict__ Wq, const float* __restrict__ Wk,
    const float* __restrict__ Wv, const float* __restrict__ Wo,
    const float* __restrict__ W1, const float* __restrict__ W2,
    const float* __restrict__ bk, const float* __restrict__ bv,
    __half* __restrict__ q16, __half* __restrict__ k16,
    __half* __restrict__ v16, __half* __restrict__ o16,
    __half* __restrict__ w116, __half* __restrict__ w216,
    float* __restrict__ bkv)
{
    int i = blockIdx.x * blockDim.x + threadIdx.x;
    if (i >= SEG_END) return;
    if (i < SEG_B) {
        const float* src; __half* dst; int j;
        if (i < SEG_W1) {
            int seg = i / SWF4; j = i - seg*SWF4;
            src = seg==0 ? Wq : seg==1 ? Wk : seg==2 ? Wv : Wo;
            dst = seg==0 ? q16 : seg==1 ? k16 : seg==2 ? v16 : o16;
        } else if (i < SEG_W2) { j = i - SEG_W1; src = W1; dst = w116; }
        else                   { j = i - SEG_W2; src = W2; dst = w216; }
        float4 v = ((const float4*)src)[j];
        __half2* o = (__half2*)(dst + (size_t)j*4);
        o[0] = __floats2half2_rn(v.x, v.y);
        o[1] = __floats2half2_rn(v.z, v.w);
    } else {
        int j = (i - SEG_B) * 4;
        #pragma unroll
        for (int e = 0; e < 4; e++) {
            int c = j + e;
            bkv[c] = (c < DM) ? bk[c] : bv[c - DM];
        }
    }
}

// ================= fp16 HMMA GEMM: C[M,N] = A[M,K] @ W[K,N] + bias =================
// B loaded directly from [K][N] weights; B fragments via ldmatrix.trans.
#define KT 64
#define AROWB 144
#define ATILEB (128*AROWB)    // 18432
#define BROWB 272
#define BTILEB (64*BROWB)     // 17408
#define GEMM_SMEM (2*(ATILEB+BTILEB))  // 71680

template<int OUTM, bool RELU, bool AREMAP>   // OUTM: 0 -> f32 C, 1 -> f16 O16
__global__ void __launch_bounds__(256) gemm_f16_kernel(
    const __half* __restrict__ A,
    const __half* __restrict__ B1, const __half* __restrict__ B2,
    int Nsplit, int ldb1, int ldb2,
    const float* __restrict__ bias,
    float* __restrict__ C, __half* __restrict__ O16,
    int M, int N, int K)
{
    extern __shared__ char smem[];
    const uint32_t sbase = smem_to_u32(smem);
    const int tid = threadIdx.x, wid = tid >> 5, lane = tid & 31;
    const int wm = wid & 1, wn = wid >> 1;
    const int m0 = blockIdx.y * 128, n0 = blockIdx.x * 128;
    const int KC = K / KT;

    // B source select (n-tile never straddles Nsplit; tiles are 128-wide)
    const __half* Bp; int ldb, nc0;
    if (n0 < Nsplit) { Bp = B1; ldb = ldb1; nc0 = n0; }
    else             { Bp = B2; ldb = ldb2; nc0 = n0 - Nsplit; }

    // A row origin (remap for Q-projection over g_full)
    int arow0;
    if (AREMAP) {
        int bq_ = blockIdx.y / 5, tq = blockIdx.y % 5;
        arow0 = bq_*LKt + LIMt + tq*128;
    } else arow0 = m0;

    float acc[4][4][4];
    #pragma unroll
    for (int i=0;i<4;i++)
        #pragma unroll
        for (int j=0;j<4;j++)
            #pragma unroll
            for (int r=0;r<4;r++) acc[i][j][r] = 0.f;

    const int lr = tid >> 3;       // A: 32 rows per iter set, 8 chunks per row
    const int lc = tid & 7;

    auto issue_chunk = [&](int c) {
        const int buf = c & 1;
        const int k0 = c * KT;
        uint32_t sA = sbase + buf * (ATILEB + BTILEB);
        uint32_t sB = sA + ATILEB;
        #pragma unroll
        for (int it = 0; it < 4; it++) {
            int r = lr + it * 32;
            int nb = (AREMAP || (m0 + r) < M) ? 16 : 0;
            cp_async16(sA + r*AROWB + lc*16,
                       A + (size_t)(arow0 + r) * K + k0 + lc*8, nb);
        }
        #pragma unroll
        for (int it = 0; it < 4; it++) {
            int e = tid + it * 256;
            int rb = e >> 4, cb = e & 15;     // 64 rows x 16 chunks
            cp_async16(sB + rb*BROWB + cb*16,
                       Bp + (size_t)(k0 + rb) * ldb + nc0 + cb*8, 16);
        }
        cp_commit();
    };

    issue_chunk(0);
    for (int c = 0; c < KC; c++) {
        if (c + 1 < KC) { issue_chunk(c + 1); cp_wait<1>(); }
        else            { cp_wait<0>(); }
        __syncthreads();

        const int buf = c & 1;
        uint32_t sA = sbase + buf * (ATILEB + BTILEB);
        uint32_t sB = sA + ATILEB;
        uint32_t aRowBase = sA + (wm*64 + (lane & 15)) * AROWB + (lane >> 4) * 16;
        uint32_t bTBase   = sB + (((lane >> 3) & 1)*8 + (lane & 7)) * BROWB
                               + (lane >> 4) * 16 + wn*64;

        #pragma unroll
        for (int ks = 0; ks < 4; ks++) {
            uint32_t bfr[4][2];
            #pragma unroll
            for (int g = 0; g < 2; g++) {
                uint32_t r0, r1, r2, r3;
                ldm_x4t(r0, r1, r2, r3, bTBase + ks*16*BROWB + g*32);
                bfr[g*2+0][0] = r0; bfr[g*2+0][1] = r1;
                bfr[g*2+1][0] = r2; bfr[g*2+1][1] = r3;
            }
            #pragma unroll
            for (int mt = 0; mt < 4; mt++) {
                uint32_t a0, a1, a2, a3;
                ldm_x4(a0, a1, a2, a3, aRowBase + mt*16*AROWB + ks*32);
                #pragma unroll
                for (int nt = 0; nt < 4; nt++)
                    mma16816(acc[mt][nt][0], acc[mt][nt][1], acc[mt][nt][2], acc[mt][nt][3],
                             a0, a1, a2, a3, bfr[nt][0], bfr[nt][1]);
            }
        }
        __syncthreads();
    }

    const int mr = lane >> 2, nc = (lane & 3) * 2;
    #pragma unroll
    for (int mt = 0; mt < 4; mt++) {
        #pragma unroll
        for (int half = 0; half < 2; half++) {
            int m = m0 + wm*64 + mt*16 + mr + half*8;
            if (m >= M) continue;
            #pragma unroll
            for (int nt = 0; nt < 4; nt++) {
                int n = n0 + wn*32 + nt*8 + nc;
                float v0 = acc[mt][nt][half*2+0] + bias[n];
                float v1 = acc[mt][nt][half*2+1] + bias[n+1];
                if (RELU) { v0 = fmaxf(v0, 0.f); v1 = fmaxf(v1, 0.f); }
                size_t o = (size_t)m * N + n;
                if (OUTM == 1) {
                    *reinterpret_cast<__half2*>(O16 + o) = __floats2half2_rn(v0, v1);
                } else {
                    C[o] = v0; C[o+1] = v1;
                }
            }
        }
    }
}

// ================= fp16 HMMA flash attention (unchanged from round 6) =================
#define ATS 72
#define ATSB 144

struct AttnSmem3 {
    __half Q[64*ATS];
    __half K[2][64*ATS], V[2][64*ATS];
    float bx[201], by[201];
    int qx[64], qy[64];
    int kx[2][64], ky[2][64];
};

#define CSC 0.18033688011116f   /* 0.125 * log2(e) */

__global__ void __launch_bounds__(128) attn_kernel(
    const __half* __restrict__ qg, const __half* __restrict__ kvg,
    const int* __restrict__ dqx, const int* __restrict__ dqy,
    const int* __restrict__ imx, const int* __restrict__ imy,
    const float* __restrict__ bias_x, const float* __restrict__ bias_y,
    __half* __restrict__ ctx)
{
    extern __shared__ char smem_raw[];
    AttnSmem3& S = *reinterpret_cast<AttnSmem3*>(smem_raw);
    const int tid = threadIdx.x;
    const int lane = tid & 31, w = tid >> 5;
    const int qt = blockIdx.x;
    const int bh = blockIdx.y;
    const int b = bh / NH, h = bh % NH;
    const int qbase = qt * 64;
    const int bLK = b * LKt;
    const int hd = h * DKh;

    const uint32_t sQ = smem_to_u32(S.Q);
    uint32_t sK[2] = { smem_to_u32(S.K[0]), smem_to_u32(S.K[1]) };
    uint32_t sV[2] = { smem_to_u32(S.V[0]), smem_to_u32(S.V[1]) };
    uint32_t sKx[2] = { smem_to_u32(S.kx[0]), smem_to_u32(S.kx[1]) };
    uint32_t sKy[2] = { smem_to_u32(S.ky[0]), smem_to_u32(S.ky[1]) };

    #pragma unroll
    for (int it = 0; it < 4; it++) {
        int ch = tid + it*128;
        int row = ch >> 3, off = (ch & 7) * 8;
        size_t g = (size_t)(b*LQ + qbase + row)*DM + hd + off;
        *(float4*)((char*)S.Q + row*ATSB + off*2) = *(const float4*)(qg + g);
    }
    const float LOG2E = 1.4426950408889634f;
    for (int i = tid; i < 201; i += 128) {
        S.bx[i] = bias_x[i*NH + h] * LOG2E;
        S.by[i] = bias_y[i*NH + h] * LOG2E;
    }
    if (tid < 64) S.qx[tid] = dqx[b*LQ + qbase + tid];
    else if (tid < 128) S.qy[tid-64] = dqy[b*LQ + qbase + (tid-64)];

    auto issue_kv = [&](int kt) {
        const int buf = kt & 1;
        const int kbase = kt * 64;
        #pragma unroll
        for (int it = 0; it < 4; it++) {
            int ch = tid + it*128;
            int row = ch >> 3, off = (ch & 7) * 8;
            int kg = kbase + row;
            int nb = kg < LKt ? 16 : 0;
            size_t g = (size_t)(bLK + kg)*KVS + hd + off;
            uint32_t so = row*ATSB + off*2;
            cp_async16(sK[buf] + so, kvg + g, nb);
            cp_async16(sV[buf] + so, kvg + g + DM, nb);
        }
        {
            int j = tid & 63;
            int kg = kbase + j;
            const int* src;
            if (tid < 64) src = (kg < LIMt) ? (imx + b*LIMt + kg) : (dqx + b*LQ + (kg - LIMt));
            else          src = (kg < LIMt) ? (imy + b*LIMt + kg) : (dqy + b*LQ + (kg - LIMt));
            uint32_t dst = (tid < 64 ? sKx[buf] : sKy[buf]) + j*4;
            cp_async4(dst, src, kg < LKt ? 4 : 0);
        }
        cp_commit();
    };

    issue_kv(0);
    __syncthreads();

    uint32_t qa[4][4];
    {
        uint32_t aBase = (w*16 + (lane & 15))*ATSB + (lane >> 4)*16;
        #pragma unroll
        for (int s = 0; s < 4; s++)
            ldm_x4(qa[s][0], qa[s][1], qa[s][2], qa[s][3], sQ + aBase + s*32);
    }

    const int r1 = w*16 + (lane >> 2);
    float oacc[8][4];
    #pragma unroll
    for (int d=0; d<8; d++)
        #pragma unroll
        for (int r=0; r<4; r++) oacc[d][r] = 0.f;
    float m1 = -1e30f, m2 = -1e30f, l1 = 0.f, l2 = 0.f;

    const int NT = (LKt + 63) / 64;
    for (int kt = 0; kt < NT; kt++) {
        if (kt > 0) __syncthreads();
        if (kt + 1 < NT) { issue_kv(kt + 1); cp_wait<1>(); }
        else             { cp_wait<0>(); }
        __syncthreads();

        const int buf = kt & 1;
        const int kbase = kt * 64;

        float sc[8][4];
        #pragma unroll
        for (int nt=0; nt<8; nt++)
            #pragma unroll
            for (int r=0; r<4; r++) sc[nt][r] = 0.f;

        uint32_t bBase = (lane & 15)*ATSB + (lane >> 4)*16;
        #pragma unroll
        for (int s = 0; s < 4; s++) {
            uint32_t bf[8][2];
            #pragma unroll
            for (int np = 0; np < 4; np++) {
                uint32_t r0, r1_, r2_, r3_;
                ldm_x4(r0, r1_, r2_, r3_, sK[buf] + bBase + np*16*ATSB + s*32);
                bf[np*2+0][0] = r0;  bf[np*2+0][1] = r2_;
                bf[np*2+1][0] = r1_; bf[np*2+1][1] = r3_;
            }
            #pragma unroll
            for (int nt = 0; nt < 8; nt++)
                mma16816(sc[nt][0], sc[nt][1], sc[nt][2], sc[nt][3],
                         qa[s][0], qa[s][1], qa[s][2], qa[s][3], bf[nt][0], bf[nt][1]);
        }

        const int qx1 = S.qx[r1],   qy1 = S.qy[r1];
        const int qx2 = S.qx[r1+8], qy2 = S.qy[r1+8];
        #pragma unroll
        for (int nt = 0; nt < 8; nt++) {
            #pragma unroll
            for (int e = 0; e < 2; e++) {
                int c = nt*8 + (lane & 3)*2 + e;
                int kxv = S.kx[buf][c], kyv = S.ky[buf][c];
                bool valid = (kbase + c) < LKt;
                int rx1 = qx1 - kxv; rx1 = rx1 < -MD ? -MD : (rx1 > MD ? MD : rx1);
                int ry1 = qy1 - kyv; ry1 = ry1 < -MD ? -MD : (ry1 > MD ? MD : ry1);
                float b1v = S.bx[rx1 + MD] + S.by[ry1 + MD];
                sc[nt][e] = valid ? fmaf(sc[nt][e], CSC, b1v) : -1e30f;
                int rx2 = qx2 - kxv; rx2 = rx2 < -MD ? -MD : (rx2 > MD ? MD : rx2);
                int ry2 = qy2 - kyv; ry2 = ry2 < -MD ? -MD : (ry2 > MD ? MD : ry2);
                float b2v = S.bx[rx2 + MD] + S.by[ry2 + MD];
                sc[nt][2+e] = valid ? fmaf(sc[nt][2+e], CSC, b2v) : -1e30f;
            }
        }

        float mx1 = -1e30f, mx2 = -1e30f;
        #pragma unroll
        for (int nt = 0; nt < 8; nt++) {
            mx1 = fmaxf(mx1, fmaxf(sc[nt][0], sc[nt][1]));
            mx2 = fmaxf(mx2, fmaxf(sc[nt][2], sc[nt][3]));
        }
        mx1 = fmaxf(mx1, __shfl_xor_sync(0xffffffffu, mx1, 1));
        mx1 = fmaxf(mx1, __shfl_xor_sync(0xffffffffu, mx1, 2));
        mx2 = fmaxf(mx2, __shfl_xor_sync(0xffffffffu, mx2, 1));
        mx2 = fmaxf(mx2, __shfl_xor_sync(0xffffffffu, mx2, 2));
        float mn1 = fmaxf(m1, mx1), mn2 = fmaxf(m2, mx2);
        float fac1 = exp2f(m1 - mn1), fac2 = exp2f(m2 - mn2);
        m1 = mn1; m2 = mn2;

        float rs1 = 0.f, rs2 = 0.f;
        #pragma unroll
        for (int nt = 0; nt < 8; nt++) {
            float p0 = exp2_poly(sc[nt][0] - m1);
            float p1 = exp2_poly(sc[nt][1] - m1);
            float p2 = exp2_poly(sc[nt][2] - m2);
            float p3 = exp2_poly(sc[nt][3] - m2);
            sc[nt][0] = p0; sc[nt][1] = p1; sc[nt][2] = p2; sc[nt][3] = p3;
            rs1 += p0 + p1; rs2 += p2 + p3;
        }
        rs1 += __shfl_xor_sync(0xffffffffu, rs1, 1);
        rs1 += __shfl_xor_sync(0xffffffffu, rs1, 2);
        rs2 += __shfl_xor_sync(0xffffffffu, rs2, 1);
        rs2 += __shfl_xor_sync(0xffffffffu, rs2, 2);
        l1 = l1 * fac1 + rs1;
        l2 = l2 * fac2 + rs2;
        #pragma unroll
        for (int d = 0; d < 8; d++) {
            oacc[d][0] *= fac1; oacc[d][1] *= fac1;
            oacc[d][2] *= fac2; oacc[d][3] *= fac2;
        }

        uint32_t pa[4][4];
        #pragma unroll
        for (int t = 0; t < 4; t++) {
            __half2 h0 = __floats2half2_rn(sc[2*t][0],   sc[2*t][1]);
            __half2 h1 = __floats2half2_rn(sc[2*t][2],   sc[2*t][3]);
            __half2 h2 = __floats2half2_rn(sc[2*t+1][0], sc[2*t+1][1]);
            __half2 h3 = __floats2half2_rn(sc[2*t+1][2], sc[2*t+1][3]);
            pa[t][0] = *reinterpret_cast<uint32_t*>(&h0);
            pa[t][1] = *reinterpret_cast<uint32_t*>(&h1);
            pa[t][2] = *reinterpret_cast<uint32_t*>(&h2);
            pa[t][3] = *reinterpret_cast<uint32_t*>(&h3);
        }

        uint32_t vBase = (((lane >> 3) & 1)*8 + (lane & 7))*ATSB + (lane >> 4)*16;
        #pragma unroll
        for (int t = 0; t < 4; t++) {
            #pragma unroll
            for (int dp = 0; dp < 4; dp++) {
                uint32_t v0, v1, v2, v3;
                ldm_x4t(v0, v1, v2, v3, sV[buf] + vBase + t*16*ATSB + dp*32);
                mma16816(oacc[dp*2][0], oacc[dp*2][1], oacc[dp*2][2], oacc[dp*2][3],
                         pa[t][0], pa[t][1], pa[t][2], pa[t][3], v0, v1);
                mma16816(oacc[dp*2+1][0], oacc[dp*2+1][1], oacc[dp*2+1][2], oacc[dp*2+1][3],
                         pa[t][0], pa[t][1], pa[t][2], pa[t][3], v2, v3);
            }
        }
    }

    float inv1 = 1.f / l1, inv2 = 1.f / l2;
    const int qrow1 = qbase + r1, qrow2 = qrow1 + 8;
    #pragma unroll
    for (int d = 0; d < 8; d++) {
        int col = hd + d*8 + (lane & 3)*2;
        {
            size_t o = (size_t)(b*LQ + qrow1)*DM + col;
            *reinterpret_cast<__half2*>(ctx + o) =
                __floats2half2_rn(oacc[d][0]*inv1, oacc[d][1]*inv1);
        }
        {
            size_t o = (size_t)(b*LQ + qrow2)*DM + col;
            *reinterpret_cast<__half2*>(ctx + o) =
                __floats2half2_rn(oacc[d][2]*inv2, oacc[d][3]*inv2);
        }
    }
}

// ================= fused add + LayerNorm =================
template<bool F16OUT>
__global__ void __launch_bounds__(256) addln_kernel(
    const float* __restrict__ A, const float* __restrict__ Cv,
    const float* __restrict__ g, const float* __restrict__ be,
    float* __restrict__ out, __half* __restrict__ O16)
{
    __shared__ float sred[256];
    const int row = blockIdx.x;
    const int tid = threadIdx.x;
    const size_t base = (size_t)row * DM;

    float x[3];
    #pragma unroll
    for (int i=0;i<3;i++) {
        int col = tid + 256*i;
        x[i] = A[base + col] + Cv[base + col];
    }
    float s = x[0] + x[1] + x[2];
    sred[tid] = s; __syncthreads();
    for (int off=128; off>0; off>>=1) {
        if (tid < off) sred[tid] += sred[tid+off];
        __syncthreads();
    }
    float mu = sred[0] * (1.f/DM);
    __syncthreads();
    float d0=x[0]-mu, d1=x[1]-mu, d2=x[2]-mu;
    sred[tid] = d0*d0 + d1*d1 + d2*d2; __syncthreads();
    for (int off=128; off>0; off>>=1) {
        if (tid < off) sred[tid] += sred[tid+off];
        __syncthreads();
    }
    float rs = rsqrtf(sred[0] * (1.f/DM) + 1e-5f);
    #pragma unroll
    for (int i=0;i<3;i++) {
        int col = tid + 256*i;
        float v = (x[i] - mu) * rs * g[col] + be[col];
        out[base + col] = v;
        if (F16OUT) O16[base + col] = __float2half_rn(v);
    }
}

// ================= launch =================
extern "C" void kernel_launch(void* const* d_in, const int* in_sizes, int n_in,
                              void* d_out, int out_size) {
    const float* docqa  = (const float*)d_in[0];
    const float* im     = (const float*)d_in[1];
    const int*   dqx    = (const int*)  d_in[2];
    const int*   dqy    = (const int*)  d_in[3];
    const int*   imx    = (const int*)  d_in[4];
    const int*   imy    = (const int*)  d_in[5];
    const float* Wq     = (const float*)d_in[6];
    const float* bq     = (const float*)d_in[7];
    const float* Wk     = (const float*)d_in[8];
    const float* bk     = (const float*)d_in[9];
    const float* Wv     = (const float*)d_in[10];
    const float* bv     = (const float*)d_in[11];
    const float* Wo     = (const float*)d_in[12];
    const float* bo     = (const float*)d_in[13];
    const float* bias_x = (const float*)d_in[14];
    const float* bias_y = (const float*)d_in[15];
    const float* W1     = (const float*)d_in[16];
    const float* b1     = (const float*)d_in[17];
    const float* W2     = (const float*)d_in[18];
    const float* b2     = (const float*)d_in[19];
    const float* g1     = (const float*)d_in[20];
    const float* be1    = (const float*)d_in[21];
    const float* g2     = (const float*)d_in[22];
    const float* be2    = (const float*)d_in[23];
    float* out = (float*)d_out;

    float *p_tmp, *p_src1, *p_bkv;
    cudaGetSymbolAddress((void**)&p_tmp,  g_tmp);
    cudaGetSymbolAddress((void**)&p_src1, g_src1);
    cudaGetSymbolAddress((void**)&p_bkv,  g_bkv);

    __half *full, *q, *kv, *ctx, *s1, *f1;
    __half *wq16, *wk16, *wv16, *wo16, *w116, *w216;
    cudaGetSymbolAddress((void**)&full, g_full);
    cudaGetSymbolAddress((void**)&q,    g_q);
    cudaGetSymbolAddress((void**)&kv,   g_kv);
    cudaGetSymbolAddress((void**)&ctx,  g_ctx);
    cudaGetSymbolAddress((void**)&s1,   g_s1);
    cudaGetSymbolAddress((void**)&f1,   g_f1);
    cudaGetSymbolAddress((void**)&wq16, g_wq16);
    cudaGetSymbolAddress((void**)&wk16, g_wk16);
    cudaGetSymbolAddress((void**)&wv16, g_wv16);
    cudaGetSymbolAddress((void**)&wo16, g_wo16);
    cudaGetSymbolAddress((void**)&w116, g_w116);
    cudaGetSymbolAddress((void**)&w216, g_w216);

    cudaFuncSetAttribute(gemm_f16_kernel<0,false,false>, cudaFuncAttributeMaxDynamicSharedMemorySize, GEMM_SMEM);
    cudaFuncSetAttribute(gemm_f16_kernel<1,false,false>, cudaFuncAttributeMaxDynamicSharedMemorySize, GEMM_SMEM);
    cudaFuncSetAttribute(gemm_f16_kernel<1,false,true >, cudaFuncAttributeMaxDynamicSharedMemorySize, GEMM_SMEM);
    cudaFuncSetAttribute(gemm_f16_kernel<1,true ,false>, cudaFuncAttributeMaxDynamicSharedMemorySize, GEMM_SMEM);
    cudaFuncSetAttribute(attn_kernel, cudaFuncAttributeMaxDynamicSharedMemorySize, (int)sizeof(AttnSmem3));

    const int MQ = Bb*LQ;     // 2560
    const int MK = Bb*LKt;    // 7744

    // launch 0: concat + fp16
    concat_f16_kernel<<<(Bb*LKt*(DM/4)+255)/256, 256>>>(im, docqa, full);
    // launch 1: all weight converts + bias concat
    wconv_all_kernel<<<(SEG_END+255)/256, 256>>>(Wq, Wk, Wv, Wo, W1, W2, bk, bv,
                                                 wq16, wk16, wv16, wo16, w116, w216, p_bkv);
    // launch 2 (profiled): fused K+V projection, N=1536 split across Wk/Wv
    gemm_f16_kernel<1,false,false><<<dim3(KVS/128, (MK+127)/128), 256, GEMM_SMEM>>>(
        full, wk16, wv16, DM, DM, DM, p_bkv, nullptr, kv, MK, KVS, DM);
    // launch 3: Q projection (A rows remapped into g_full's docqa region)
    gemm_f16_kernel<1,false,true><<<dim3(DM/128, MQ/128), 256, GEMM_SMEM>>>(
        full, wq16, wq16, DM, DM, DM, bq, nullptr, q, MQ, DM, DM);
    // launch 4: attention
    attn_kernel<<<dim3(LQ/64, Bb*NH), 128, sizeof(AttnSmem3)>>>(
        q, kv, dqx, dqy, imx, imy, bias_x, bias_y, ctx);
    // launch 5: output projection
    gemm_f16_kernel<0,false,false><<<dim3(DM/128, MQ/128), 256, GEMM_SMEM>>>(
        ctx, wo16, wo16, DM, DM, DM, bo, p_tmp, nullptr, MQ, DM, DM);
    // launch 6: add + LN1
    addln_kernel<true><<<MQ, 256>>>(docqa, p_tmp, g1, be1, p_src1, s1);
    // launch 7: FFN up + ReLU
    gemm_f16_kernel<1,true,false><<<dim3(DFFn/128, MQ/128), 256, GEMM_SMEM>>>(
        s1, w116, w116, DFFn, DFFn, DFFn, b1, nullptr, f1, MQ, DFFn, DM);
    // launch 8: FFN down
    gemm_f16_kernel<0,false,false><<<dim3(DM/128, MQ/128), 256, GEMM_SMEM>>>(
        f1, w216, w216, DM, DM, DM, b2, p_tmp, nullptr, MQ, DM, DFFn);
    // launch 9: add + LN2 -> out
    addln_kernel<false><<<MQ, 256>>>(p_src1, p_tmp, g2, be2, out, nullptr);
}

// round 8
// speedup vs baseline: 6.7747x; 1.0039x over previous
#include <cuda_runtime.h>
#include <cuda_fp16.h>
#include <math.h>
#include <stdint.h>

#define Bb 4
#define LQ 640
#define LIMt 1296
#define LKt 1936
#define DM 768
#define NH 12
#define DKh 64
#define DFFn 3072
#define MD 100
#define KVS 1536   // kv row stride
#define MQn (Bb*LQ)    // 2560
#define MKn (Bb*LKt)   // 7744

// ================= helpers =================
__device__ __forceinline__ uint32_t smem_to_u32(const void* p) {
    uint32_t a;
    asm("{ .reg .u64 t; cvta.to.shared.u64 t, %1; cvt.u32.u64 %0, t; }" : "=r"(a) : "l"(p));
    return a;
}
__device__ __forceinline__ void cp_async16(uint32_t dst, const void* src, int src_bytes) {
    asm volatile("cp.async.cg.shared.global [%0], [%1], 16, %2;"
                 :: "r"(dst), "l"(src), "r"(src_bytes) : "memory");
}
__device__ __forceinline__ void cp_async4(uint32_t dst, const void* src, int src_bytes) {
    asm volatile("cp.async.ca.shared.global [%0], [%1], 4, %2;"
                 :: "r"(dst), "l"(src), "r"(src_bytes) : "memory");
}
__device__ __forceinline__ void cp_commit() {
    asm volatile("cp.async.commit_group;" ::: "memory");
}
template<int N>
__device__ __forceinline__ void cp_wait() {
    asm volatile("cp.async.wait_group %0;" :: "n"(N) : "memory");
}
__device__ __forceinline__ void ldm_x4(uint32_t& r0, uint32_t& r1, uint32_t& r2, uint32_t& r3,
                                       uint32_t addr) {
    asm volatile("ldmatrix.sync.aligned.m8n8.x4.shared.b16 {%0,%1,%2,%3}, [%4];"
                 : "=r"(r0), "=r"(r1), "=r"(r2), "=r"(r3) : "r"(addr));
}
__device__ __forceinline__ void ldm_x4t(uint32_t& r0, uint32_t& r1, uint32_t& r2, uint32_t& r3,
                                        uint32_t addr) {
    asm volatile("ldmatrix.sync.aligned.m8n8.x4.trans.shared.b16 {%0,%1,%2,%3}, [%4];"
                 : "=r"(r0), "=r"(r1), "=r"(r2), "=r"(r3) : "r"(addr));
}
__device__ __forceinline__ void mma16816(float& d0, float& d1, float& d2, float& d3,
                                         uint32_t a0, uint32_t a1, uint32_t a2, uint32_t a3,
                                         uint32_t b0, uint32_t b1) {
    asm volatile("mma.sync.aligned.m16n8k16.row.col.f32.f16.f16.f32 "
                 "{%0,%1,%2,%3}, {%4,%5,%6,%7}, {%8,%9}, {%0,%1,%2,%3};"
                 : "+f"(d0), "+f"(d1), "+f"(d2), "+f"(d3)
                 : "r"(a0), "r"(a1), "r"(a2), "r"(a3), "r"(b0), "r"(b1));
}
__device__ __forceinline__ float exp2_poly(float a) {
    a = fmaxf(a, -126.f);
    float z = a + 12582912.f;
    int ir = __float_as_int(z) - 0x4B400000;
    float r = z - 12582912.f;
    float f = a - r;
    float p = 0.0096181291f;
    p = fmaf(p, f, 0.0555041087f);
    p = fmaf(p, f, 0.2402265070f);
    p = fmaf(p, f, 0.6931471806f);
    p = fmaf(p, f, 1.0f);
    return p * __int_as_float((ir + 127) << 23);
}

// ================= scratch =================
__device__ float g_tmp [Bb*LQ*DM];
__device__ float g_src1[Bb*LQ*DM];
__device__ float g_bkv [KVS];

__device__ __half g_full[Bb*LKt*DM];
__device__ __half g_q   [Bb*LQ*DM];
__device__ __half g_kv  [Bb*LKt*KVS];
__device__ __half g_ctx [Bb*LQ*DM];
__device__ __half g_s1  [Bb*LQ*DM];
__device__ __half g_f1  [Bb*LQ*DFFn];
// weights in ORIGINAL [K][N] layout, fp16
__device__ __half g_wq16[DM*DM];
__device__ __half g_wk16[DM*DM];
__device__ __half g_wv16[DM*DM];
__device__ __half g_wo16[DM*DM];
__device__ __half g_w116[DM*DFFn];
__device__ __half g_w216[DFFn*DM];

// ================= converts =================
__global__ void concat_f16_kernel(const float* __restrict__ im, const float* __restrict__ doc,
                                  __half* __restrict__ O) {
    int i = blockIdx.x * blockDim.x + threadIdx.x;
    const int total4 = Bb*LKt*(DM/4);
    if (i >= total4) return;
    int d4 = i % (DM/4); int bt = i / (DM/4);
    int b = bt / LKt, t = bt % LKt;
    const float* src = (t < LIMt) ? im + ((size_t)b*LIMt + t)*DM
                                  : doc + ((size_t)b*LQ + (t - LIMt))*DM;
    float4 v = *(const float4*)(src + d4*4);
    __half2* o = (__half2*)(O + (size_t)i*4);
    o[0] = __floats2half2_rn(v.x, v.y);
    o[1] = __floats2half2_rn(v.z, v.w);
}

// all 6 weights fp32->fp16 (layout preserved) + bias concat
#define SWF4   147456
#define W1F4   589824
#define SEG_W1 (4*SWF4)
#define SEG_W2 (SEG_W1 + W1F4)
#define SEG_B  (SEG_W2 + W1F4)
#define SEG_END (SEG_B + KVS/4)

__global__ void wconv_all_kernel(
    const float* __restrict__ Wq, const float* __restrict__ Wk,
    const float* __restrict__ Wv, const float* __restrict__ Wo,
    const float* __restrict__ W1, const float* __restrict__ W2,
    const float* __restrict__ bk, const float* __restrict__ bv,
    __half* __restrict__ q16, __half* __restrict__ k16,
    __half* __restrict__ v16, __half* __restrict__ o16,
    __half* __restrict__ w116, __half* __restrict__ w216,
    float* __restrict__ bkv)
{
    int i = blockIdx.x * blockDim.x + threadIdx.x;
    if (i >= SEG_END) return;
    if (i < SEG_B) {
        const float* src; __half* dst; int j;
        if (i < SEG_W1) {
            int seg = i / SWF4; j = i - seg*SWF4;
            src = seg==0 ? Wq : seg==1 ? Wk : seg==2 ? Wv : Wo;
            dst = seg==0 ? q16 : seg==1 ? k16 : seg==2 ? v16 : o16;
        } else if (i < SEG_W2) { j = i - SEG_W1; src = W1; dst = w116; }
        else                   { j = i - SEG_W2; src = W2; dst = w216; }
        float4 v = ((const float4*)src)[j];
        __half2* o = (__half2*)(dst + (size_t)j*4);
        o[0] = __floats2half2_rn(v.x, v.y);
        o[1] = __floats2half2_rn(v.z, v.w);
    } else {
        int j = (i - SEG_B) * 4;
        #pragma unroll
        for (int e = 0; e < 4; e++) {
            int c = j + e;
            bkv[c] = (c < DM) ? bk[c] : bv[c - DM];
        }
    }
}

// ================= fp16 HMMA GEMM body: C[128,128] tile of A[M,K] @ W[K,N] + bias =================
// 3-stage cp.async pipeline; B direct from [K][N] weights via ldmatrix.trans.
#define KT 64
#define AROWB 144
#define ATILEB (128*AROWB)    // 18432
#define BROWB 272
#define BTILEB (64*BROWB)     // 17408
#define STAGEB (ATILEB+BTILEB)
#define GEMM_SMEM (3*STAGEB)  // 107520

template<int OUTM, bool RELU>   // OUTM: 0 -> f32 C, 1 -> f16 O16
__device__ __forceinline__ void gemm_body(
    const __half* __restrict__ A, int arow0, bool guard, int M, int m0,
    const __half* __restrict__ Bp, int ldb, int nc0,
    const float* __restrict__ bias, int n0,
    float* __restrict__ C, __half* __restrict__ O16, int ldo,
    int K, uint32_t sbase)
{
    const int tid = threadIdx.x, wid = tid >> 5, lane = tid & 31;
    const int wm = wid & 1, wn = wid >> 1;
    const int KC = K / KT;

    float acc[4][4][4];
    #pragma unroll
    for (int i=0;i<4;i++)
        #pragma unroll
        for (int j=0;j<4;j++)
            #pragma unroll
            for (int r=0;r<4;r++) acc[i][j][r] = 0.f;

    const int lr = tid >> 3;
    const int lc = tid & 7;

    auto issue_chunk = [&](int c) {
        const int buf = c % 3;
        const int k0 = c * KT;
        uint32_t sA = sbase + buf * STAGEB;
        uint32_t sB = sA + ATILEB;
        #pragma unroll
        for (int it = 0; it < 4; it++) {
            int r = lr + it * 32;
            int nb = (!guard || (m0 + r) < M) ? 16 : 0;
            cp_async16(sA + r*AROWB + lc*16,
                       A + (size_t)(arow0 + r) * K + k0 + lc*8, nb);
        }
        #pragma unroll
        for (int it = 0; it < 4; it++) {
            int e = tid + it * 256;
            int rb = e >> 4, cb = e & 15;
            cp_async16(sB + rb*BROWB + cb*16,
                       Bp + (size_t)(k0 + rb) * ldb + nc0 + cb*8, 16);
        }
        cp_commit();
    };

    issue_chunk(0);
    issue_chunk(1);
    for (int c = 0; c < KC; c++) {
        if (c + 2 < KC)      { issue_chunk(c + 2); cp_wait<2>(); }
        else if (c + 1 < KC) { cp_wait<1>(); }
        else                 { cp_wait<0>(); }
        __syncthreads();

        const int buf = c % 3;
        uint32_t sA = sbase + buf * STAGEB;
        uint32_t sB = sA + ATILEB;
        uint32_t aRowBase = sA + (wm*64 + (lane & 15)) * AROWB + (lane >> 4) * 16;
        uint32_t bTBase   = sB + (((lane >> 3) & 1)*8 + (lane & 7)) * BROWB
                               + (lane >> 4) * 16 + wn*64;

        #pragma unroll
        for (int ks = 0; ks < 4; ks++) {
            uint32_t bfr[4][2];
            #pragma unroll
            for (int g = 0; g < 2; g++) {
                uint32_t r0, r1, r2, r3;
                ldm_x4t(r0, r1, r2, r3, bTBase + ks*16*BROWB + g*32);
                bfr[g*2+0][0] = r0; bfr[g*2+0][1] = r1;
                bfr[g*2+1][0] = r2; bfr[g*2+1][1] = r3;
            }
            #pragma unroll
            for (int mt = 0; mt < 4; mt++) {
                uint32_t a0, a1, a2, a3;
                ldm_x4(a0, a1, a2, a3, aRowBase + mt*16*AROWB + ks*32);
                #pragma unroll
                for (int nt = 0; nt < 4; nt++)
                    mma16816(acc[mt][nt][0], acc[mt][nt][1], acc[mt][nt][2], acc[mt][nt][3],
                             a0, a1, a2, a3, bfr[nt][0], bfr[nt][1]);
            }
        }
        __syncthreads();
    }

    const int mr = lane >> 2, nc = (lane & 3) * 2;
    #pragma unroll
    for (int mt = 0; mt < 4; mt++) {
        #pragma unroll
        for (int half = 0; half < 2; half++) {
            int m = m0 + wm*64 + mt*16 + mr + half*8;
            if (guard && m >= M) continue;
            #pragma unroll
            for (int nt = 0; nt < 4; nt++) {
                int n = n0 + wn*32 + nt*8 + nc;
                float v0 = acc[mt][nt][half*2+0] + bias[n];
                float v1 = acc[mt][nt][half*2+1] + bias[n+1];
                if (RELU) { v0 = fmaxf(v0, 0.f); v1 = fmaxf(v1, 0.f); }
                size_t o = (size_t)m * ldo + n;
                if (OUTM == 1) {
                    *reinterpret_cast<__half2*>(O16 + o) = __floats2half2_rn(v0, v1);
                } else {
                    C[o] = v0; C[o+1] = v1;
                }
            }
        }
    }
}

// generic GEMM (Wo, FFN1, FFN2)
template<int OUTM, bool RELU>
__global__ void __launch_bounds__(256,2) gemm_f16_kernel(
    const __half* __restrict__ A, const __half* __restrict__ Bp, int ldb,
    const float* __restrict__ bias,
    float* __restrict__ C, __half* __restrict__ O16,
    int M, int N, int K)
{
    extern __shared__ char smem[];
    int m0 = blockIdx.y * 128, n0 = blockIdx.x * 128;
    gemm_body<OUTM,RELU>(A, m0, true, M, m0, Bp, ldb, n0, bias, n0,
                         C, O16, N, K, smem_to_u32(smem));
}

// merged Q + KV projection: 852 blocks (732 KV tiles + 120 Q tiles)
__global__ void __launch_bounds__(256,2) qkv_kernel(
    const __half* __restrict__ full,
    const __half* __restrict__ wq, const __half* __restrict__ wk, const __half* __restrict__ wv,
    const float* __restrict__ bq, const float* __restrict__ bkv,
    __half* __restrict__ q, __half* __restrict__ kv)
{
    extern __shared__ char smem[];
    uint32_t sbase = smem_to_u32(smem);
    int id = blockIdx.x;
    if (id < 732) {
        int bx = id % 12, by = id / 12;
        int m0 = by*128, n0 = bx*128;
        const __half* Bp = (n0 < DM) ? wk : wv;
        int nc0 = (n0 < DM) ? n0 : n0 - DM;
        gemm_body<1,false>(full, m0, true, MKn, m0, Bp, DM, nc0, bkv, n0,
                           nullptr, kv, KVS, DM, sbase);
    } else {
        int id2 = id - 732;
        int bx = id2 % 6, by = id2 / 6;
        int m0 = by*128, n0 = bx*128;
        int arow0 = (by/5)*LKt + LIMt + (by%5)*128;
        gemm_body<1,false>(full, arow0, false, MQn, m0, wq, DM, n0, bq, n0,
                           nullptr, q, DM, DM, sbase);
    }
}

// ================= fp16 HMMA flash attention (unchanged) =================
#define ATS 72
#define ATSB 144

struct AttnSmem3 {
    __half Q[64*ATS];
    __half K[2][64*ATS], V[2][64*ATS];
    float bx[201], by[201];
    int qx[64], qy[64];
    int kx[2][64], ky[2][64];
};

#define CSC 0.18033688011116f   /* 0.125 * log2(e) */

__global__ void __launch_bounds__(128) attn_kernel(
    const __half* __restrict__ qg, const __half* __restrict__ kvg,
    const int* __restrict__ dqx, const int* __restrict__ dqy,
    const int* __restrict__ imx, const int* __restrict__ imy,
    const float* __restrict__ bias_x, const float* __restrict__ bias_y,
    __half* __restrict__ ctx)
{
    extern __shared__ char smem_raw[];
    AttnSmem3& S = *reinterpret_cast<AttnSmem3*>(smem_raw);
    const int tid = threadIdx.x;
    const int lane = tid & 31, w = tid >> 5;
    const int qt = blockIdx.x;
    const int bh = blockIdx.y;
    const int b = bh / NH, h = bh % NH;
    const int qbase = qt * 64;
    const int bLK = b * LKt;
    const int hd = h * DKh;

    const uint32_t sQ = smem_to_u32(S.Q);
    uint32_t sK[2] = { smem_to_u32(S.K[0]), smem_to_u32(S.K[1]) };
    uint32_t sV[2] = { smem_to_u32(S.V[0]), smem_to_u32(S.V[1]) };
    uint32_t sKx[2] = { smem_to_u32(S.kx[0]), smem_to_u32(S.kx[1]) };
    uint32_t sKy[2] = { smem_to_u32(S.ky[0]), smem_to_u32(S.ky[1]) };

    #pragma unroll
    for (int it = 0; it < 4; it++) {
        int ch = tid + it*128;
        int row = ch >> 3, off = (ch & 7) * 8;
        size_t g = (size_t)(b*LQ + qbase + row)*DM + hd + off;
        *(float4*)((char*)S.Q + row*ATSB + off*2) = *(const float4*)(qg + g);
    }
    const float LOG2E = 1.4426950408889634f;
    for (int i = tid; i < 201; i += 128) {
        S.bx[i] = bias_x[i*NH + h] * LOG2E;
        S.by[i] = bias_y[i*NH + h] * LOG2E;
    }
    if (tid < 64) S.qx[tid] = dqx[b*LQ + qbase + tid];
    else if (tid < 128) S.qy[tid-64] = dqy[b*LQ + qbase + (tid-64)];

    auto issue_kv = [&](int kt) {
        const int buf = kt & 1;
        const int kbase = kt * 64;
        #pragma unroll
        for (int it = 0; it < 4; it++) {
            int ch = tid + it*128;
            int row = ch >> 3, off = (ch & 7) * 8;
            int kg = kbase + row;
            int nb = kg < LKt ? 16 : 0;
            size_t g = (size_t)(bLK + kg)*KVS + hd + off;
            uint32_t so = row*ATSB + off*2;
            cp_async16(sK[buf] + so, kvg + g, nb);
            cp_async16(sV[buf] + so, kvg + g + DM, nb);
        }
        {
            int j = tid & 63;
            int kg = kbase + j;
            const int* src;
            if (tid < 64) src = (kg < LIMt) ? (imx + b*LIMt + kg) : (dqx + b*LQ + (kg - LIMt));
            else          src = (kg < LIMt) ? (imy + b*LIMt + kg) : (dqy + b*LQ + (kg - LIMt));
            uint32_t dst = (tid < 64 ? sKx[buf] : sKy[buf]) + j*4;
            cp_async4(dst, src, kg < LKt ? 4 : 0);
        }
        cp_commit();
    };

    issue_kv(0);
    __syncthreads();

    uint32_t qa[4][4];
    {
        uint32_t aBase = (w*16 + (lane & 15))*ATSB + (lane >> 4)*16;
        #pragma unroll
        for (int s = 0; s < 4; s++)
            ldm_x4(qa[s][0], qa[s][1], qa[s][2], qa[s][3], sQ + aBase + s*32);
    }

    const int r1 = w*16 + (lane >> 2);
    float oacc[8][4];
    #pragma unroll
    for (int d=0; d<8; d++)
        #pragma unroll
        for (int r=0; r<4; r++) oacc[d][r] = 0.f;
    float m1 = -1e30f, m2 = -1e30f, l1 = 0.f, l2 = 0.f;

    const int NT = (LKt + 63) / 64;
    for (int kt = 0; kt < NT; kt++) {
        if (kt > 0) __syncthreads();
        if (kt + 1 < NT) { issue_kv(kt + 1); cp_wait<1>(); }
        else             { cp_wait<0>(); }
        __syncthreads();

        const int buf = kt & 1;
        const int kbase = kt * 64;

        float sc[8][4];
        #pragma unroll
        for (int nt=0; nt<8; nt++)
            #pragma unroll
            for (int r=0; r<4; r++) sc[nt][r] = 0.f;

        uint32_t bBase = (lane & 15)*ATSB + (lane >> 4)*16;
        #pragma unroll
        for (int s = 0; s < 4; s++) {
            uint32_t bf[8][2];
            #pragma unroll
            for (int np = 0; np < 4; np++) {
                uint32_t r0, r1_, r2_, r3_;
                ldm_x4(r0, r1_, r2_, r3_, sK[buf] + bBase + np*16*ATSB + s*32);
                bf[np*2+0][0] = r0;  bf[np*2+0][1] = r2_;
                bf[np*2+1][0] = r1_; bf[np*2+1][1] = r3_;
            }
            #pragma unroll
            for (int nt = 0; nt < 8; nt++)
                mma16816(sc[nt][0], sc[nt][1], sc[nt][2], sc[nt][3],
                         qa[s][0], qa[s][1], qa[s][2], qa[s][3], bf[nt][0], bf[nt][1]);
        }

        const int qx1 = S.qx[r1],   qy1 = S.qy[r1];
        const int qx2 = S.qx[r1+8], qy2 = S.qy[r1+8];
        #pragma unroll
        for (int nt = 0; nt < 8; nt++) {
            #pragma unroll
            for (int e = 0; e < 2; e++) {
                int c = nt*8 + (lane & 3)*2 + e;
                int kxv = S.kx[buf][c], kyv = S.ky[buf][c];
                bool valid = (kbase + c) < LKt;
                int rx1 = qx1 - kxv; rx1 = rx1 < -MD ? -MD : (rx1 > MD ? MD : rx1);
                int ry1 = qy1 - kyv; ry1 = ry1 < -MD ? -MD : (ry1 > MD ? MD : ry1);
                float b1v = S.bx[rx1 + MD] + S.by[ry1 + MD];
                sc[nt][e] = valid ? fmaf(sc[nt][e], CSC, b1v) : -1e30f;
                int rx2 = qx2 - kxv; rx2 = rx2 < -MD ? -MD : (rx2 > MD ? MD : rx2);
                int ry2 = qy2 - kyv; ry2 = ry2 < -MD ? -MD : (ry2 > MD ? MD : ry2);
                float b2v = S.bx[rx2 + MD] + S.by[ry2 + MD];
                sc[nt][2+e] = valid ? fmaf(sc[nt][2+e], CSC, b2v) : -1e30f;
            }
        }

        float mx1 = -1e30f, mx2 = -1e30f;
        #pragma unroll
        for (int nt = 0; nt < 8; nt++) {
            mx1 = fmaxf(mx1, fmaxf(sc[nt][0], sc[nt][1]));
            mx2 = fmaxf(mx2, fmaxf(sc[nt][2], sc[nt][3]));
        }
        mx1 = fmaxf(mx1, __shfl_xor_sync(0xffffffffu, mx1, 1));
        mx1 = fmaxf(mx1, __shfl_xor_sync(0xffffffffu, mx1, 2));
        mx2 = fmaxf(mx2, __shfl_xor_sync(0xffffffffu, mx2, 1));
        mx2 = fmaxf(mx2, __shfl_xor_sync(0xffffffffu, mx2, 2));
        float mn1 = fmaxf(m1, mx1), mn2 = fmaxf(m2, mx2);
        float fac1 = exp2f(m1 - mn1), fac2 = exp2f(m2 - mn2);
        m1 = mn1; m2 = mn2;

        float rs1 = 0.f, rs2 = 0.f;
        #pragma unroll
        for (int nt = 0; nt < 8; nt++) {
            float p0 = exp2_poly(sc[nt][0] - m1);
            float p1 = exp2_poly(sc[nt][1] - m1);
            float p2 = exp2_poly(sc[nt][2] - m2);
            float p3 = exp2_poly(sc[nt][3] - m2);
            sc[nt][0] = p0; sc[nt][1] = p1; sc[nt][2] = p2; sc[nt][3] = p3;
            rs1 += p0 + p1; rs2 += p2 + p3;
        }
        rs1 += __shfl_xor_sync(0xffffffffu, rs1, 1);
        rs1 += __shfl_xor_sync(0xffffffffu, rs1, 2);
        rs2 += __shfl_xor_sync(0xffffffffu, rs2, 1);
        rs2 += __shfl_xor_sync(0xffffffffu, rs2, 2);
        l1 = l1 * fac1 + rs1;
        l2 = l2 * fac2 + rs2;
        #pragma unroll
        for (int d = 0; d < 8; d++) {
            oacc[d][0] *= fac1; oacc[d][1] *= fac1;
            oacc[d][2] *= fac2; oacc[d][3] *= fac2;
        }

        uint32_t pa[4][4];
        #pragma unroll
        for (int t = 0; t < 4; t++) {
            __half2 h0 = __floats2half2_rn(sc[2*t][0],   sc[2*t][1]);
            __half2 h1 = __floats2half2_rn(sc[2*t][2],   sc[2*t][3]);
            __half2 h2 = __floats2half2_rn(sc[2*t+1][0], sc[2*t+1][1]);
            __half2 h3 = __floats2half2_rn(sc[2*t+1][2], sc[2*t+1][3]);
            pa[t][0] = *reinterpret_cast<uint32_t*>(&h0);
            pa[t][1] = *reinterpret_cast<uint32_t*>(&h1);
            pa[t][2] = *reinterpret_cast<uint32_t*>(&h2);
            pa[t][3] = *reinterpret_cast<uint32_t*>(&h3);
        }

        uint32_t vBase = (((lane >> 3) & 1)*8 + (lane & 7))*ATSB + (lane >> 4)*16;
        #pragma unroll
        for (int t = 0; t < 4; t++) {
            #pragma unroll
            for (int dp = 0; dp < 4; dp++) {
                uint32_t v0, v1, v2, v3;
                ldm_x4t(v0, v1, v2, v3, sV[buf] + vBase + t*16*ATSB + dp*32);
                mma16816(oacc[dp*2][0], oacc[dp*2][1], oacc[dp*2][2], oacc[dp*2][3],
                         pa[t][0], pa[t][1], pa[t][2], pa[t][3], v0, v1);
                mma16816(oacc[dp*2+1][0], oacc[dp*2+1][1], oacc[dp*2+1][2], oacc[dp*2+1][3],
                         pa[t][0], pa[t][1], pa[t][2], pa[t][3], v2, v3);
            }
        }
    }

    float inv1 = 1.f / l1, inv2 = 1.f / l2;
    const int qrow1 = qbase + r1, qrow2 = qrow1 + 8;
    #pragma unroll
    for (int d = 0; d < 8; d++) {
        int col = hd + d*8 + (lane & 3)*2;
        {
            size_t o = (size_t)(b*LQ + qrow1)*DM + col;
            *reinterpret_cast<__half2*>(ctx + o) =
                __floats2half2_rn(oacc[d][0]*inv1, oacc[d][1]*inv1);
        }
        {
            size_t o = (size_t)(b*LQ + qrow2)*DM + col;
            *reinterpret_cast<__half2*>(ctx + o) =
                __floats2half2_rn(oacc[d][2]*inv2, oacc[d][3]*inv2);
        }
    }
}

// ================= fused add + LayerNorm =================
template<bool F16OUT>
__global__ void __launch_bounds__(256) addln_kernel(
    const float* __restrict__ A, const float* __restrict__ Cv,
    const float* __restrict__ g, const float* __restrict__ be,
    float* __restrict__ out, __half* __restrict__ O16)
{
    __shared__ float sred[256];
    const int row = blockIdx.x;
    const int tid = threadIdx.x;
    const size_t base = (size_t)row * DM;

    float x[3];
    #pragma unroll
    for (int i=0;i<3;i++) {
        int col = tid + 256*i;
        x[i] = A[base + col] + Cv[base + col];
    }
    float s = x[0] + x[1] + x[2];
    sred[tid] = s; __syncthreads();
    for (int off=128; off>0; off>>=1) {
        if (tid < off) sred[tid] += sred[tid+off];
        __syncthreads();
    }
    float mu = sred[0] * (1.f/DM);
    __syncthreads();
    float d0=x[0]-mu, d1=x[1]-mu, d2=x[2]-mu;
    sred[tid] = d0*d0 + d1*d1 + d2*d2; __syncthreads();
    for (int off=128; off>0; off>>=1) {
        if (tid < off) sred[tid] += sred[tid+off];
        __syncthreads();
    }
    float rs = rsqrtf(sred[0] * (1.f/DM) + 1e-5f);
    #pragma unroll
    for (int i=0;i<3;i++) {
        int col = tid + 256*i;
        float v = (x[i] - mu) * rs * g[col] + be[col];
        out[base + col] = v;
        if (F16OUT) O16[base + col] = __float2half_rn(v);
    }
}

// ================= launch =================
extern "C" void kernel_launch(void* const* d_in, const int* in_sizes, int n_in,
                              void* d_out, int out_size) {
    const float* docqa  = (const float*)d_in[0];
    const float* im     = (const float*)d_in[1];
    const int*   dqx    = (const int*)  d_in[2];
    const int*   dqy    = (const int*)  d_in[3];
    const int*   imx    = (const int*)  d_in[4];
    const int*   imy    = (const int*)  d_in[5];
    const float* Wq     = (const float*)d_in[6];
    const float* bq     = (const float*)d_in[7];
    const float* Wk     = (const float*)d_in[8];
    const float* bk     = (const float*)d_in[9];
    const float* Wv     = (const float*)d_in[10];
    const float* bv     = (const float*)d_in[11];
    const float* Wo     = (const float*)d_in[12];
    const float* bo     = (const float*)d_in[13];
    const float* bias_x = (const float*)d_in[14];
    const float* bias_y = (const float*)d_in[15];
    const float* W1     = (const float*)d_in[16];
    const float* b1     = (const float*)d_in[17];
    const float* W2     = (const float*)d_in[18];
    const float* b2     = (const float*)d_in[19];
    const float* g1     = (const float*)d_in[20];
    const float* be1    = (const float*)d_in[21];
    const float* g2     = (const float*)d_in[22];
    const float* be2    = (const float*)d_in[23];
    float* out = (float*)d_out;

    float *p_tmp, *p_src1, *p_bkv;
    cudaGetSymbolAddress((void**)&p_tmp,  g_tmp);
    cudaGetSymbolAddress((void**)&p_src1, g_src1);
    cudaGetSymbolAddress((void**)&p_bkv,  g_bkv);

    __half *full, *q, *kv, *ctx, *s1, *f1;
    __half *wq16, *wk16, *wv16, *wo16, *w116, *w216;
    cudaGetSymbolAddress((void**)&full, g_full);
    cudaGetSymbolAddress((void**)&q,    g_q);
    cudaGetSymbolAddress((void**)&kv,   g_kv);
    cudaGetSymbolAddress((void**)&ctx,  g_ctx);
    cudaGetSymbolAddress((void**)&s1,   g_s1);
    cudaGetSymbolAddress((void**)&f1,   g_f1);
    cudaGetSymbolAddress((void**)&wq16, g_wq16);
    cudaGetSymbolAddress((void**)&wk16, g_wk16);
    cudaGetSymbolAddress((void**)&wv16, g_wv16);
    cudaGetSymbolAddress((void**)&wo16, g_wo16);
    cudaGetSymbolAddress((void**)&w116, g_w116);
    cudaGetSymbolAddress((void**)&w216, g_w216);

    cudaFuncSetAttribute(qkv_kernel, cudaFuncAttributeMaxDynamicSharedMemorySize, GEMM_SMEM);
    cudaFuncSetAttribute(gemm_f16_kernel<0,false>, cudaFuncAttributeMaxDynamicSharedMemorySize, GEMM_SMEM);
    cudaFuncSetAttribute(gemm_f16_kernel<1,false>, cudaFuncAttributeMaxDynamicSharedMemorySize, GEMM_SMEM);
    cudaFuncSetAttribute(gemm_f16_kernel<1,true >, cudaFuncAttributeMaxDynamicSharedMemorySize, GEMM_SMEM);
    cudaFuncSetAttribute(attn_kernel, cudaFuncAttributeMaxDynamicSharedMemorySize, (int)sizeof(AttnSmem3));

    // launch 0: concat + fp16
    concat_f16_kernel<<<(Bb*LKt*(DM/4)+255)/256, 256>>>(im, docqa, full);
    // launch 1: weight converts + bias concat
    wconv_all_kernel<<<(SEG_END+255)/256, 256>>>(Wq, Wk, Wv, Wo, W1, W2, bk, bv,
                                                 wq16, wk16, wv16, wo16, w116, w216, p_bkv);
    // launch 2: merged Q + KV projections (852 blocks)
    qkv_kernel<<<852, 256, GEMM_SMEM>>>(full, wq16, wk16, wv16, bq, p_bkv, q, kv);
    // launch 3 (profiled next round): attention
    attn_kernel<<<dim3(LQ/64, Bb*NH), 128, sizeof(AttnSmem3)>>>(
        q, kv, dqx, dqy, imx, imy, bias_x, bias_y, ctx);
    // launch 4: output projection
    gemm_f16_kernel<0,false><<<dim3(DM/128, MQn/128), 256, GEMM_SMEM>>>(
        ctx, wo16, DM, bo, p_tmp, nullptr, MQn, DM, DM);
    // launch 5: add + LN1
    addln_kernel<true><<<MQn, 256>>>(docqa, p_tmp, g1, be1, p_src1, s1);
    // launch 6: FFN up + ReLU
    gemm_f16_kernel<1,true><<<dim3(DFFn/128, MQn/128), 256, GEMM_SMEM>>>(
        s1, w116, DFFn, b1, nullptr, f1, MQn, DFFn, DM);
    // launch 7: FFN down
    gemm_f16_kernel<0,false><<<dim3(DM/128, MQn/128), 256, GEMM_SMEM>>>(
        f1, w216, DM, b2, p_tmp, nullptr, MQn, DM, DFFn);
    // launch 8: add + LN2 -> out
    addln_kernel<false><<<MQn, 256>>>(p_src1, p_tmp, g2, be2, out, nullptr);
}